// round 1
// baseline (speedup 1.0000x reference)
#include <cuda_runtime.h>
#include <math.h>
#include <stdint.h>

// ----------------------------------------------------------------------------
// Transformer forward: 6 layers, B=4, N=1024, D=1024, H=16, hd=64, MLP=4096
// Round 0 baseline: fp32 SIMT tiled GEMMs + materialized attention scores.
// ----------------------------------------------------------------------------

static constexpr int BATCH  = 4;
static constexpr int SEQ    = 1024;
static constexpr int DIM    = 1024;
static constexpr int HEADS  = 16;
static constexpr int HD     = 64;
static constexpr int MLPD   = 4096;
static constexpr int DEPTH  = 6;
static constexpr int TOK    = BATCH * SEQ;          // 4096
static constexpr float EPS  = 1e-5f;
static constexpr float SCALE = 0.03125f;            // DIM^-0.5 = 1/32

// Scratch (device globals -- allocation-free per harness rules)
__device__ float g_x   [(size_t)TOK * DIM];                     // residual stream
__device__ float g_y   [(size_t)TOK * DIM];                     // LN output
__device__ float g_qkv [(size_t)TOK * 3 * DIM];                 // [b,n,3,h,hd]
__device__ float g_attn[(size_t)TOK * DIM];                     // attn out [t,d]
__device__ float g_hid [(size_t)TOK * MLPD];                    // MLP hidden
__device__ float g_S   [(size_t)BATCH * HEADS * SEQ * SEQ];     // scores (256 MB)

// ----------------------------------------------------------------------------
__global__ void copy_kernel(const float* __restrict__ in, float* __restrict__ out, int n) {
    int i = blockIdx.x * blockDim.x + threadIdx.x;
    if (i < n) out[i] = in[i];
}

// ----------------------------------------------------------------------------
// LayerNorm: one block per token row of 1024
__global__ void ln_kernel(const float* __restrict__ x,
                          const float* __restrict__ w,
                          const float* __restrict__ b,
                          float* __restrict__ y) {
    int row = blockIdx.x;
    const float* xr = x + (size_t)row * DIM;
    __shared__ float red[256];
    int t = threadIdx.x;

    float s = 0.f;
    for (int i = t; i < DIM; i += 256) s += xr[i];
    red[t] = s; __syncthreads();
    for (int o = 128; o > 0; o >>= 1) { if (t < o) red[t] += red[t + o]; __syncthreads(); }
    float mu = red[0] * (1.0f / DIM);
    __syncthreads();

    float v = 0.f;
    for (int i = t; i < DIM; i += 256) { float d = xr[i] - mu; v += d * d; }
    red[t] = v; __syncthreads();
    for (int o = 128; o > 0; o >>= 1) { if (t < o) red[t] += red[t + o]; __syncthreads(); }
    float rstd = rsqrtf(red[0] * (1.0f / DIM) + EPS);

    float* yr = y + (size_t)row * DIM;
    for (int i = t; i < DIM; i += 256)
        yr[i] = (xr[i] - mu) * rstd * w[i] + b[i];
}

// ----------------------------------------------------------------------------
// Generic SGEMM: C[M,N] = A[M,K] @ B[K,N] (+epilogue)
// EPI: 0=none, 1=+bias, 2=+bias then gelu, 3=+bias +residual
// All M,N,K multiples of tile dims (asserted by the fixed problem shapes).
template<int EPI>
__global__ void sgemm(const float* __restrict__ A, const float* __restrict__ Bw,
                      const float* __restrict__ bias, const float* __restrict__ res,
                      float* __restrict__ C, int M, int N, int K) {
    constexpr int BM = 128, BN = 64, BK = 16;
    __shared__ float As[BK][BM];       // transposed A tile
    __shared__ float Bs[BK][BN];

    int tid = threadIdx.x;             // 256 threads
    int bm = blockIdx.y * BM, bn = blockIdx.x * BN;
    int tx = tid & 15, ty = tid >> 4;  // 16x16 thread grid, each 8x4 outputs

    float acc[8][4];
    #pragma unroll
    for (int i = 0; i < 8; i++)
        #pragma unroll
        for (int j = 0; j < 4; j++) acc[i][j] = 0.f;

    for (int k0 = 0; k0 < K; k0 += BK) {
        // Load A tile 128x16 as float4 (2 per thread), store transposed
        #pragma unroll
        for (int l = 0; l < 2; l++) {
            int s = tid * 2 + l;             // 0..511
            int row = s >> 2, kq = (s & 3) * 4;
            float4 a = *(const float4*)(A + (size_t)(bm + row) * K + k0 + kq);
            As[kq + 0][row] = a.x; As[kq + 1][row] = a.y;
            As[kq + 2][row] = a.z; As[kq + 3][row] = a.w;
        }
        // Load B tile 16x64 as float4 (1 per thread)
        {
            int row = tid >> 4, nq = (tid & 15) * 4;
            float4 bv = *(const float4*)(Bw + (size_t)(k0 + row) * N + bn + nq);
            *(float4*)&Bs[row][nq] = bv;
        }
        __syncthreads();

        #pragma unroll
        for (int k = 0; k < BK; k++) {
            float4 a0 = *(const float4*)&As[k][ty * 8];
            float4 a1 = *(const float4*)&As[k][ty * 8 + 4];
            float4 bv = *(const float4*)&Bs[k][tx * 4];
            float ra[8] = {a0.x, a0.y, a0.z, a0.w, a1.x, a1.y, a1.z, a1.w};
            float rb[4] = {bv.x, bv.y, bv.z, bv.w};
            #pragma unroll
            for (int i = 0; i < 8; i++)
                #pragma unroll
                for (int j = 0; j < 4; j++)
                    acc[i][j] += ra[i] * rb[j];
        }
        __syncthreads();
    }

    #pragma unroll
    for (int i = 0; i < 8; i++) {
        int m = bm + ty * 8 + i;
        #pragma unroll
        for (int j = 0; j < 4; j++) {
            int n = bn + tx * 4 + j;
            float v = acc[i][j];
            if (EPI >= 1) v += bias[n];
            if (EPI == 2) v = 0.5f * v * (1.0f + erff(v * 0.70710678118654752f));
            if (EPI == 3) v += res[(size_t)m * N + n];
            C[(size_t)m * N + n] = v;
        }
    }
}

// ----------------------------------------------------------------------------
// S[bh,i,j] = scale * sum_d Q[b,i,h,d] * K[b,j,h,d]
// grid: (jtile=16, itile=16, bh=64), block 256
__global__ void qk_kernel(const float* __restrict__ qkv, float* __restrict__ S) {
    int bh = blockIdx.z;
    int b = bh >> 4, h = bh & 15;
    int i0 = blockIdx.y * 64, j0 = blockIdx.x * 64;

    __shared__ float Qs[64][65];
    __shared__ float Ks[64][65];
    int tid = threadIdx.x;
    const size_t tokStride = 3 * DIM;   // 3072
    const float* base = qkv + (size_t)b * SEQ * tokStride + (size_t)h * HD;

    for (int idx = tid; idx < 64 * 64; idx += 256) {
        int r = idx >> 6, d = idx & 63;
        Qs[r][d] = base[(size_t)(i0 + r) * tokStride + d];            // sel 0 (Q)
        Ks[r][d] = base[(size_t)(j0 + r) * tokStride + DIM + d];      // sel 1 (K)
    }
    __syncthreads();

    int tx = tid & 15, ty = tid >> 4;
    float acc[4][4];
    #pragma unroll
    for (int i = 0; i < 4; i++)
        #pragma unroll
        for (int j = 0; j < 4; j++) acc[i][j] = 0.f;

    #pragma unroll 8
    for (int d = 0; d < 64; d++) {
        float rq[4], rk[4];
        #pragma unroll
        for (int i = 0; i < 4; i++) rq[i] = Qs[ty * 4 + i][d];
        #pragma unroll
        for (int j = 0; j < 4; j++) rk[j] = Ks[tx * 4 + j][d];
        #pragma unroll
        for (int i = 0; i < 4; i++)
            #pragma unroll
            for (int j = 0; j < 4; j++)
                acc[i][j] += rq[i] * rk[j];
    }

    float* Sb = S + (size_t)bh * SEQ * SEQ;
    #pragma unroll
    for (int i = 0; i < 4; i++)
        #pragma unroll
        for (int j = 0; j < 4; j++)
            Sb[(size_t)(i0 + ty * 4 + i) * SEQ + (j0 + tx * 4 + j)] = acc[i][j] * SCALE;
}

// ----------------------------------------------------------------------------
// Row softmax over length-1024 rows. grid = 64*1024 blocks.
__global__ void softmax_kernel(float* __restrict__ S) {
    size_t row = blockIdx.x;
    float* p = S + row * SEQ;
    __shared__ float red[256];
    int t = threadIdx.x;

    float m = -1e30f;
    for (int i = t; i < SEQ; i += 256) m = fmaxf(m, p[i]);
    red[t] = m; __syncthreads();
    for (int o = 128; o > 0; o >>= 1) { if (t < o) red[t] = fmaxf(red[t], red[t + o]); __syncthreads(); }
    m = red[0]; __syncthreads();

    float s = 0.f;
    for (int i = t; i < SEQ; i += 256) { float e = __expf(p[i] - m); p[i] = e; s += e; }
    red[t] = s; __syncthreads();
    for (int o = 128; o > 0; o >>= 1) { if (t < o) red[t] += red[t + o]; __syncthreads(); }
    float inv = 1.0f / red[0];

    for (int i = t; i < SEQ; i += 256) p[i] *= inv;
}

// ----------------------------------------------------------------------------
// O[b,i,h,d] = sum_j S[bh,i,j] * V[b,j,h,d]; O laid out [tok, DIM]
// grid: (itile=16, bh=64), block 256
__global__ void sv_kernel(const float* __restrict__ S, const float* __restrict__ qkv,
                          float* __restrict__ O) {
    int bh = blockIdx.y;
    int b = bh >> 4, h = bh & 15;
    int i0 = blockIdx.x * 64;

    __shared__ float Ss[64][65];
    __shared__ float Vs[64][65];
    int tid = threadIdx.x, tx = tid & 15, ty = tid >> 4;
    const size_t tokStride = 3 * DIM;
    const float* vbase = qkv + (size_t)b * SEQ * tokStride + 2 * DIM + (size_t)h * HD;
    const float* Sb = S + (size_t)bh * SEQ * SEQ;

    float acc[4][4];
    #pragma unroll
    for (int i = 0; i < 4; i++)
        #pragma unroll
        for (int j = 0; j < 4; j++) acc[i][j] = 0.f;

    for (int j0 = 0; j0 < SEQ; j0 += 64) {
        for (int idx = tid; idx < 64 * 64; idx += 256) {
            int r = idx >> 6, c = idx & 63;
            Ss[r][c] = Sb[(size_t)(i0 + r) * SEQ + j0 + c];
            Vs[r][c] = vbase[(size_t)(j0 + r) * tokStride + c];
        }
        __syncthreads();

        #pragma unroll 8
        for (int j = 0; j < 64; j++) {
            float rs[4], rv[4];
            #pragma unroll
            for (int i = 0; i < 4; i++) rs[i] = Ss[ty * 4 + i][j];
            #pragma unroll
            for (int c = 0; c < 4; c++) rv[c] = Vs[j][tx * 4 + c];
            #pragma unroll
            for (int i = 0; i < 4; i++)
                #pragma unroll
                for (int c = 0; c < 4; c++)
                    acc[i][c] += rs[i] * rv[c];
        }
        __syncthreads();
    }

    float* ob = O + ((size_t)b * SEQ + i0) * DIM + (size_t)h * HD;
    #pragma unroll
    for (int i = 0; i < 4; i++)
        #pragma unroll
        for (int c = 0; c < 4; c++)
            ob[(size_t)(ty * 4 + i) * DIM + tx * 4 + c] = acc[i][c];
}

// ----------------------------------------------------------------------------
extern "C" void kernel_launch(void* const* d_in, const int* in_sizes, int n_in,
                              void* d_out, int out_size) {
    const float* x_in   = (const float*)d_in[0];
    const float* ln1_w  = (const float*)d_in[1];
    const float* ln1_b  = (const float*)d_in[2];
    const float* qkv_w  = (const float*)d_in[3];
    const float* qkv_b  = (const float*)d_in[4];
    const float* proj_w = (const float*)d_in[5];
    const float* proj_b = (const float*)d_in[6];
    const float* ln2_w  = (const float*)d_in[7];
    const float* ln2_b  = (const float*)d_in[8];
    const float* mlp_w1 = (const float*)d_in[9];
    const float* mlp_b1 = (const float*)d_in[10];
    const float* mlp_w2 = (const float*)d_in[11];
    const float* mlp_b2 = (const float*)d_in[12];
    float* out = (float*)d_out;

    float *px, *py, *pqkv, *pattn, *phid, *pS;
    cudaGetSymbolAddress((void**)&px,    g_x);
    cudaGetSymbolAddress((void**)&py,    g_y);
    cudaGetSymbolAddress((void**)&pqkv,  g_qkv);
    cudaGetSymbolAddress((void**)&pattn, g_attn);
    cudaGetSymbolAddress((void**)&phid,  g_hid);
    cudaGetSymbolAddress((void**)&pS,    g_S);

    const int nx = TOK * DIM;
    copy_kernel<<<(nx + 255) / 256, 256>>>(x_in, px, nx);

    for (int l = 0; l < DEPTH; l++) {
        const float* qw  = qkv_w  + (size_t)l * DIM * 3 * DIM;
        const float* qb  = qkv_b  + (size_t)l * 3 * DIM;
        const float* pw  = proj_w + (size_t)l * DIM * DIM;
        const float* pb  = proj_b + (size_t)l * DIM;
        const float* w1  = mlp_w1 + (size_t)l * DIM * MLPD;
        const float* b1  = mlp_b1 + (size_t)l * MLPD;
        const float* w2  = mlp_w2 + (size_t)l * MLPD * DIM;
        const float* b2  = mlp_b2 + (size_t)l * DIM;

        // ---- attention sublayer ----
        ln_kernel<<<TOK, 256>>>(px, ln1_w + (size_t)l * DIM, ln1_b + (size_t)l * DIM, py);
        sgemm<1><<<dim3(3 * DIM / 64, TOK / 128), 256>>>(py, qw, qb, nullptr, pqkv,
                                                         TOK, 3 * DIM, DIM);
        qk_kernel<<<dim3(16, 16, BATCH * HEADS), 256>>>(pqkv, pS);
        softmax_kernel<<<BATCH * HEADS * SEQ, 256>>>(pS);
        sv_kernel<<<dim3(16, BATCH * HEADS), 256>>>(pS, pqkv, pattn);
        sgemm<3><<<dim3(DIM / 64, TOK / 128), 256>>>(pattn, pw, pb, px, px,
                                                     TOK, DIM, DIM);

        // ---- MLP sublayer ----
        ln_kernel<<<TOK, 256>>>(px, ln2_w + (size_t)l * DIM, ln2_b + (size_t)l * DIM, py);
        sgemm<2><<<dim3(MLPD / 64, TOK / 128), 256>>>(py, w1, b1, nullptr, phid,
                                                      TOK, MLPD, DIM);
        sgemm<3><<<dim3(DIM / 64, TOK / 128), 256>>>(phid, w2, b2, px, px,
                                                     TOK, DIM, MLPD);
    }

    copy_kernel<<<(nx + 255) / 256, 256>>>(px, out, nx);
}

// round 3
// speedup vs baseline: 1.6604x; 1.6604x over previous
#include <cuda_runtime.h>
#include <cuda_bf16.h>
#include <math.h>
#include <stdint.h>

// ----------------------------------------------------------------------------
// Transformer forward: 6 layers, B=4, N=1024, D=1024, H=16, hd=64, MLP=4096
// Round 2: dense GEMMs on mma.sync bf16 (HMMA) with bf16x3 compensation.
// (tcgen05 unavailable: harness compiles PTX for compute_103, not _103a.)
// ----------------------------------------------------------------------------

static constexpr int BATCH  = 4;
static constexpr int SEQ    = 1024;
static constexpr int DIM    = 1024;
static constexpr int HEADS  = 16;
static constexpr int HD     = 64;
static constexpr int MLPD   = 4096;
static constexpr int DEPTH  = 6;
static constexpr int TOK    = BATCH * SEQ;          // 4096
static constexpr float EPS  = 1e-5f;
static constexpr float SCALE = 0.03125f;            // DIM^-0.5

// ---------------- scratch (device globals; no allocation) -------------------
__device__ float         g_x   [(size_t)TOK * DIM];
__device__ __nv_bfloat16 g_yh  [(size_t)TOK * DIM];
__device__ __nv_bfloat16 g_yl  [(size_t)TOK * DIM];
__device__ float         g_qkv [(size_t)TOK * 3 * DIM];
__device__ __nv_bfloat16 g_ah  [(size_t)TOK * DIM];
__device__ __nv_bfloat16 g_al  [(size_t)TOK * DIM];
__device__ __nv_bfloat16 g_hh  [(size_t)TOK * MLPD];
__device__ __nv_bfloat16 g_hl  [(size_t)TOK * MLPD];
__device__ float         g_S   [(size_t)BATCH * HEADS * SEQ * SEQ];

// transposed + hi/lo-split weights (written per launch; deterministic)
__device__ __nv_bfloat16 g_wq_h[(size_t)DEPTH * 3 * DIM * DIM];
__device__ __nv_bfloat16 g_wq_l[(size_t)DEPTH * 3 * DIM * DIM];
__device__ __nv_bfloat16 g_wp_h[(size_t)DEPTH * DIM * DIM];
__device__ __nv_bfloat16 g_wp_l[(size_t)DEPTH * DIM * DIM];
__device__ __nv_bfloat16 g_w1_h[(size_t)DEPTH * MLPD * DIM];
__device__ __nv_bfloat16 g_w1_l[(size_t)DEPTH * MLPD * DIM];
__device__ __nv_bfloat16 g_w2_h[(size_t)DEPTH * DIM * MLPD];
__device__ __nv_bfloat16 g_w2_l[(size_t)DEPTH * DIM * MLPD];

// ---------------------------- PTX helpers -----------------------------------
__device__ __forceinline__ uint32_t smem_u32(const void* p) {
    uint32_t a;
    asm("{ .reg .u64 t; cvta.to.shared.u64 t, %1; cvt.u32.u64 %0, t; }"
        : "=r"(a) : "l"(p));
    return a;
}

__device__ __forceinline__ void ldsm4(uint32_t* r, uint32_t a) {
    asm volatile("ldmatrix.sync.aligned.m8n8.x4.shared.b16 {%0,%1,%2,%3}, [%4];"
        : "=r"(r[0]), "=r"(r[1]), "=r"(r[2]), "=r"(r[3]) : "r"(a));
}

__device__ __forceinline__ void mma16816(float* c, const uint32_t* a,
                                         uint32_t b0, uint32_t b1) {
    asm volatile("mma.sync.aligned.m16n8k16.row.col.f32.bf16.bf16.f32 "
        "{%0,%1,%2,%3}, {%4,%5,%6,%7}, {%8,%9}, {%0,%1,%2,%3};"
        : "+f"(c[0]), "+f"(c[1]), "+f"(c[2]), "+f"(c[3])
        : "r"(a[0]), "r"(a[1]), "r"(a[2]), "r"(a[3]), "r"(b0), "r"(b1));
}

#define CP_ASYNC16(saddr, gptr) \
    asm volatile("cp.async.cg.shared.global [%0], [%1], 16;" :: "r"(saddr), "l"(gptr))
#define CP_COMMIT() asm volatile("cp.async.commit_group;" ::: "memory")
#define CP_WAIT(n)  asm volatile("cp.async.wait_group %0;" :: "n"(n) : "memory")

// ----------------------------------------------------------------------------
__global__ void copy_kernel(const float* __restrict__ in, float* __restrict__ out, int n) {
    int i = blockIdx.x * blockDim.x + threadIdx.x;
    if (i < n) out[i] = in[i];
}

// ----------------------------------------------------------------------------
// Weight transpose + hi/lo split: W [L,K,N] fp32 -> Wt_hi/lo [L,N,K] bf16
__global__ void wconvert(const float* __restrict__ W, __nv_bfloat16* __restrict__ Th,
                         __nv_bfloat16* __restrict__ Tl, int K, int N) {
    __shared__ float t[32][33];
    size_t loff = (size_t)blockIdx.z * K * N;
    const float* Wl = W + loff;
    int n0 = blockIdx.x * 32, k0 = blockIdx.y * 32;
    #pragma unroll
    for (int i = 0; i < 4; i++) {
        int k = k0 + threadIdx.y + i * 8;
        t[threadIdx.y + i * 8][threadIdx.x] = Wl[(size_t)k * N + n0 + threadIdx.x];
    }
    __syncthreads();
    #pragma unroll
    for (int i = 0; i < 4; i++) {
        int n = n0 + threadIdx.y + i * 8;
        float v = t[threadIdx.x][threadIdx.y + i * 8];
        __nv_bfloat16 h = __float2bfloat16(v);
        float lo = v - __bfloat162float(h);
        size_t o = loff + (size_t)n * K + k0 + threadIdx.x;
        Th[o] = h;
        Tl[o] = __float2bfloat16(lo);
    }
}

// ----------------------------------------------------------------------------
// LayerNorm with hi/lo bf16 split output
__global__ void ln_split(const float* __restrict__ x,
                         const float* __restrict__ w,
                         const float* __restrict__ b,
                         __nv_bfloat16* __restrict__ yh,
                         __nv_bfloat16* __restrict__ yl) {
    int row = blockIdx.x;
    const float* xr = x + (size_t)row * DIM;
    __shared__ float red[256];
    int t = threadIdx.x;

    float s = 0.f;
    for (int i = t; i < DIM; i += 256) s += xr[i];
    red[t] = s; __syncthreads();
    for (int o = 128; o > 0; o >>= 1) { if (t < o) red[t] += red[t + o]; __syncthreads(); }
    float mu = red[0] * (1.0f / DIM);
    __syncthreads();

    float v = 0.f;
    for (int i = t; i < DIM; i += 256) { float d = xr[i] - mu; v += d * d; }
    red[t] = v; __syncthreads();
    for (int o = 128; o > 0; o >>= 1) { if (t < o) red[t] += red[t + o]; __syncthreads(); }
    float rstd = rsqrtf(red[0] * (1.0f / DIM) + EPS);

    for (int i = t; i < DIM; i += 256) {
        float y = (xr[i] - mu) * rstd * w[i] + b[i];
        __nv_bfloat16 h = __float2bfloat16(y);
        yh[(size_t)row * DIM + i] = h;
        yl[(size_t)row * DIM + i] = __float2bfloat16(y - __bfloat162float(h));
    }
}

// ----------------------------------------------------------------------------
// Tensor-core GEMM via mma.sync bf16 (bf16x3): C[M,N] = A[M,K] @ W[K,N]
// A given as hi/lo bf16 [M,K]; W given pre-transposed hi/lo [N,K] (K-major).
// EPI: 1 = +bias -> fp32 Cf;  2 = +bias,gelu -> bf16 hi/lo;  3 = +bias+res -> Cf
// CTA 128x128, BK=32, 8 warps (2m x 4n), warp tile 64x32, 3-stage cp.async.
template<int EPI>
__global__ void __launch_bounds__(256, 1)
gemm_mma(const __nv_bfloat16* __restrict__ Ah, const __nv_bfloat16* __restrict__ Al,
         const __nv_bfloat16* __restrict__ Bh, const __nv_bfloat16* __restrict__ Bl,
         const float* __restrict__ bias, const float* __restrict__ res,
         float* __restrict__ Cf, __nv_bfloat16* __restrict__ Ch,
         __nv_bfloat16* __restrict__ Cl, int M, int N, int K) {
    constexpr int STAGES = 3;
    constexpr int ROWB   = 80;            // padded row stride (bytes) for 32 bf16
    constexpr int TILEB  = 128 * ROWB;    // 10240 B per operand tile
    constexpr int STAGEB = 4 * TILEB;     // 40960 B per stage

    extern __shared__ char smem[];
    uint32_t sb = smem_u32(smem);
    int tid = threadIdx.x, lane = tid & 31, wid = tid >> 5;
    int bm = blockIdx.y * 128, bn = blockIdx.x * 128;
    int warp_m = wid >> 2, warp_n = wid & 3;

    const __nv_bfloat16* srcs[4] = { Ah + (size_t)bm * K, Al + (size_t)bm * K,
                                     Bh + (size_t)bn * K, Bl + (size_t)bn * K };
    int nch = K >> 5;

    // ldmatrix per-thread addressing pieces
    int g = lane >> 3;
    uint32_t rowsel = (uint32_t)(((g & 1) << 3) + (lane & 7));  // 0..15
    uint32_t colsel = (uint32_t)((g >> 1) * 16);                // byte offset 0/16

    float acc[4][4][4];
    #pragma unroll
    for (int i = 0; i < 4; i++)
        #pragma unroll
        for (int j = 0; j < 4; j++)
            #pragma unroll
            for (int q = 0; q < 4; q++) acc[i][j][q] = 0.f;

    // ---- async tile loader: 8 x 16B per thread per stage ----
    auto issue = [&](int ch) {
        int k0 = ch << 5;
        uint32_t sbase = sb + (uint32_t)(ch % STAGES) * STAGEB;
        #pragma unroll
        for (int j = 0; j < 8; j++) {
            int c2 = j * 256 + tid;
            int op = c2 >> 9, idx = c2 & 511, row = idx >> 2, ck = idx & 3;
            const __nv_bfloat16* gp = srcs[op] + (size_t)row * K + k0 + ck * 8;
            uint32_t sa = sbase + (uint32_t)(op * TILEB + row * ROWB + ck * 16);
            CP_ASYNC16(sa, gp);
        }
    };

    #pragma unroll
    for (int s = 0; s < STAGES; s++) { issue(s); CP_COMMIT(); }

    for (int c = 0; c < nch; c++) {
        CP_WAIT(STAGES - 1);
        __syncthreads();
        uint32_t st = sb + (uint32_t)((c % STAGES) * STAGEB);

        #pragma unroll
        for (int kh = 0; kh < 2; kh++) {
            uint32_t kb = (uint32_t)(kh * 32) + colsel;
            uint32_t ah[4][4], al[4][4], bh[2][4], bl[2][4];
            #pragma unroll
            for (int mi = 0; mi < 4; mi++) {
                uint32_t r = (uint32_t)(warp_m * 64 + mi * 16) + rowsel;
                ldsm4(ah[mi], st + r * ROWB + kb);
                ldsm4(al[mi], st + TILEB + r * ROWB + kb);
            }
            #pragma unroll
            for (int ni = 0; ni < 2; ni++) {
                uint32_t r = (uint32_t)(warp_n * 32 + ni * 16) + rowsel;
                ldsm4(bh[ni], st + 2 * TILEB + r * ROWB + kb);
                ldsm4(bl[ni], st + 3 * TILEB + r * ROWB + kb);
            }
            // product 1: Ah * Bh
            #pragma unroll
            for (int mi = 0; mi < 4; mi++)
                #pragma unroll
                for (int nj = 0; nj < 4; nj++)
                    mma16816(acc[mi][nj], ah[mi], bh[nj >> 1][nj & 1], bh[nj >> 1][(nj & 1) + 2]);
            // product 2: Ah * Bl
            #pragma unroll
            for (int mi = 0; mi < 4; mi++)
                #pragma unroll
                for (int nj = 0; nj < 4; nj++)
                    mma16816(acc[mi][nj], ah[mi], bl[nj >> 1][nj & 1], bl[nj >> 1][(nj & 1) + 2]);
            // product 3: Al * Bh
            #pragma unroll
            for (int mi = 0; mi < 4; mi++)
                #pragma unroll
                for (int nj = 0; nj < 4; nj++)
                    mma16816(acc[mi][nj], al[mi], bh[nj >> 1][nj & 1], bh[nj >> 1][(nj & 1) + 2]);
        }
        __syncthreads();
        if (c + STAGES < nch) issue(c + STAGES);
        CP_COMMIT();
    }

    // ---- epilogue ----
    #pragma unroll
    for (int mi = 0; mi < 4; mi++) {
        int r0 = bm + warp_m * 64 + mi * 16 + (lane >> 2);
        #pragma unroll
        for (int nj = 0; nj < 4; nj++) {
            int cc = bn + warp_n * 32 + nj * 8 + (lane & 3) * 2;
            float b0 = bias[cc], b1 = bias[cc + 1];
            #pragma unroll
            for (int half = 0; half < 2; half++) {
                int r = r0 + half * 8;
                float v0 = acc[mi][nj][half * 2 + 0] + b0;
                float v1 = acc[mi][nj][half * 2 + 1] + b1;
                size_t o = (size_t)r * N + cc;
                if (EPI == 2) {
                    v0 = 0.5f * v0 * (1.0f + erff(v0 * 0.70710678118654752f));
                    v1 = 0.5f * v1 * (1.0f + erff(v1 * 0.70710678118654752f));
                    __nv_bfloat16 h0 = __float2bfloat16(v0);
                    __nv_bfloat16 h1 = __float2bfloat16(v1);
                    __nv_bfloat162 hp; hp.x = h0; hp.y = h1;
                    *(__nv_bfloat162*)(Ch + o) = hp;
                    __nv_bfloat162 lp;
                    lp.x = __float2bfloat16(v0 - __bfloat162float(h0));
                    lp.y = __float2bfloat16(v1 - __bfloat162float(h1));
                    *(__nv_bfloat162*)(Cl + o) = lp;
                } else {
                    if (EPI == 3) {
                        v0 += res[o];
                        v1 += res[o + 1];
                    }
                    float2 f2; f2.x = v0; f2.y = v1;
                    *(float2*)(Cf + o) = f2;
                }
            }
        }
    }
}

// ----------------------------------------------------------------------------
// S[bh,i,j] = scale * sum_d Q[b,i,h,d] * K[b,j,h,d]
__global__ void qk_kernel(const float* __restrict__ qkv, float* __restrict__ S) {
    int bh = blockIdx.z;
    int b = bh >> 4, h = bh & 15;
    int i0 = blockIdx.y * 64, j0 = blockIdx.x * 64;

    __shared__ float Qs[64][65];
    __shared__ float Ks[64][65];
    int tid = threadIdx.x;
    const size_t tokStride = 3 * DIM;
    const float* base = qkv + (size_t)b * SEQ * tokStride + (size_t)h * HD;

    for (int idx = tid; idx < 64 * 64; idx += 256) {
        int r = idx >> 6, d = idx & 63;
        Qs[r][d] = base[(size_t)(i0 + r) * tokStride + d];
        Ks[r][d] = base[(size_t)(j0 + r) * tokStride + DIM + d];
    }
    __syncthreads();

    int tx = tid & 15, ty = tid >> 4;
    float acc[4][4];
    #pragma unroll
    for (int i = 0; i < 4; i++)
        #pragma unroll
        for (int j = 0; j < 4; j++) acc[i][j] = 0.f;

    #pragma unroll 8
    for (int d = 0; d < 64; d++) {
        float rq[4], rk[4];
        #pragma unroll
        for (int i = 0; i < 4; i++) rq[i] = Qs[ty * 4 + i][d];
        #pragma unroll
        for (int j = 0; j < 4; j++) rk[j] = Ks[tx * 4 + j][d];
        #pragma unroll
        for (int i = 0; i < 4; i++)
            #pragma unroll
            for (int j = 0; j < 4; j++)
                acc[i][j] += rq[i] * rk[j];
    }

    float* Sb = S + (size_t)bh * SEQ * SEQ;
    #pragma unroll
    for (int i = 0; i < 4; i++)
        #pragma unroll
        for (int j = 0; j < 4; j++)
            Sb[(size_t)(i0 + ty * 4 + i) * SEQ + (j0 + tx * 4 + j)] = acc[i][j] * SCALE;
}

// ----------------------------------------------------------------------------
__global__ void softmax_kernel(float* __restrict__ S) {
    size_t row = blockIdx.x;
    float* p = S + row * SEQ;
    __shared__ float red[256];
    int t = threadIdx.x;

    float m = -1e30f;
    for (int i = t; i < SEQ; i += 256) m = fmaxf(m, p[i]);
    red[t] = m; __syncthreads();
    for (int o = 128; o > 0; o >>= 1) { if (t < o) red[t] = fmaxf(red[t], red[t + o]); __syncthreads(); }
    m = red[0]; __syncthreads();

    float s = 0.f;
    for (int i = t; i < SEQ; i += 256) { float e = __expf(p[i] - m); p[i] = e; s += e; }
    red[t] = s; __syncthreads();
    for (int o = 128; o > 0; o >>= 1) { if (t < o) red[t] += red[t + o]; __syncthreads(); }
    float inv = 1.0f / red[0];

    for (int i = t; i < SEQ; i += 256) p[i] *= inv;
}

// ----------------------------------------------------------------------------
// O = S @ V; output as bf16 hi/lo (feeds proj GEMM)
__global__ void sv_kernel(const float* __restrict__ S, const float* __restrict__ qkv,
                          __nv_bfloat16* __restrict__ Oh, __nv_bfloat16* __restrict__ Ol) {
    int bh = blockIdx.y;
    int b = bh >> 4, h = bh & 15;
    int i0 = blockIdx.x * 64;

    __shared__ float Ss[64][65];
    __shared__ float Vs[64][65];
    int tid = threadIdx.x, tx = tid & 15, ty = tid >> 4;
    const size_t tokStride = 3 * DIM;
    const float* vbase = qkv + (size_t)b * SEQ * tokStride + 2 * DIM + (size_t)h * HD;
    const float* Sb = S + (size_t)bh * SEQ * SEQ;

    float acc[4][4];
    #pragma unroll
    for (int i = 0; i < 4; i++)
        #pragma unroll
        for (int j = 0; j < 4; j++) acc[i][j] = 0.f;

    for (int j0 = 0; j0 < SEQ; j0 += 64) {
        for (int idx = tid; idx < 64 * 64; idx += 256) {
            int r = idx >> 6, c = idx & 63;
            Ss[r][c] = Sb[(size_t)(i0 + r) * SEQ + j0 + c];
            Vs[r][c] = vbase[(size_t)(j0 + r) * tokStride + c];
        }
        __syncthreads();

        #pragma unroll 8
        for (int j = 0; j < 64; j++) {
            float rs[4], rv[4];
            #pragma unroll
            for (int i = 0; i < 4; i++) rs[i] = Ss[ty * 4 + i][j];
            #pragma unroll
            for (int c = 0; c < 4; c++) rv[c] = Vs[j][tx * 4 + c];
            #pragma unroll
            for (int i = 0; i < 4; i++)
                #pragma unroll
                for (int c = 0; c < 4; c++)
                    acc[i][c] += rs[i] * rv[c];
        }
        __syncthreads();
    }

    size_t obase = ((size_t)b * SEQ + i0) * DIM + (size_t)h * HD;
    #pragma unroll
    for (int i = 0; i < 4; i++)
        #pragma unroll
        for (int c = 0; c < 4; c++) {
            float v = acc[i][c];
            __nv_bfloat16 hh = __float2bfloat16(v);
            size_t o = obase + (size_t)(ty * 4 + i) * DIM + tx * 4 + c;
            Oh[o] = hh;
            Ol[o] = __float2bfloat16(v - __bfloat162float(hh));
        }
}

// ----------------------------------------------------------------------------
extern "C" void kernel_launch(void* const* d_in, const int* in_sizes, int n_in,
                              void* d_out, int out_size) {
    const float* x_in   = (const float*)d_in[0];
    const float* ln1_w  = (const float*)d_in[1];
    const float* ln1_b  = (const float*)d_in[2];
    const float* qkv_w  = (const float*)d_in[3];
    const float* qkv_b  = (const float*)d_in[4];
    const float* proj_w = (const float*)d_in[5];
    const float* proj_b = (const float*)d_in[6];
    const float* ln2_w  = (const float*)d_in[7];
    const float* ln2_b  = (const float*)d_in[8];
    const float* mlp_w1 = (const float*)d_in[9];
    const float* mlp_b1 = (const float*)d_in[10];
    const float* mlp_w2 = (const float*)d_in[11];
    const float* mlp_b2 = (const float*)d_in[12];
    float* out = (float*)d_out;

    float *px, *pqkv, *pS;
    __nv_bfloat16 *pyh, *pyl, *pah, *pal, *phh, *phl;
    __nv_bfloat16 *wqh, *wql, *wph, *wpl, *w1h, *w1l, *w2h, *w2l;
    cudaGetSymbolAddress((void**)&px,   g_x);
    cudaGetSymbolAddress((void**)&pyh,  g_yh);
    cudaGetSymbolAddress((void**)&pyl,  g_yl);
    cudaGetSymbolAddress((void**)&pqkv, g_qkv);
    cudaGetSymbolAddress((void**)&pah,  g_ah);
    cudaGetSymbolAddress((void**)&pal,  g_al);
    cudaGetSymbolAddress((void**)&phh,  g_hh);
    cudaGetSymbolAddress((void**)&phl,  g_hl);
    cudaGetSymbolAddress((void**)&pS,   g_S);
    cudaGetSymbolAddress((void**)&wqh,  g_wq_h);
    cudaGetSymbolAddress((void**)&wql,  g_wq_l);
    cudaGetSymbolAddress((void**)&wph,  g_wp_h);
    cudaGetSymbolAddress((void**)&wpl,  g_wp_l);
    cudaGetSymbolAddress((void**)&w1h,  g_w1_h);
    cudaGetSymbolAddress((void**)&w1l,  g_w1_l);
    cudaGetSymbolAddress((void**)&w2h,  g_w2_h);
    cudaGetSymbolAddress((void**)&w2l,  g_w2_l);

    const int SMEMSZ = 3 * 4 * 128 * 80;   // 122880 B
    cudaFuncSetAttribute(gemm_mma<1>, cudaFuncAttributeMaxDynamicSharedMemorySize, SMEMSZ);
    cudaFuncSetAttribute(gemm_mma<2>, cudaFuncAttributeMaxDynamicSharedMemorySize, SMEMSZ);
    cudaFuncSetAttribute(gemm_mma<3>, cudaFuncAttributeMaxDynamicSharedMemorySize, SMEMSZ);

    // weight transpose + split (per launch; deterministic)
    dim3 blk(32, 8);
    wconvert<<<dim3(3 * DIM / 32, DIM / 32, DEPTH), blk>>>(qkv_w,  wqh, wql, DIM,  3 * DIM);
    wconvert<<<dim3(DIM / 32,     DIM / 32, DEPTH), blk>>>(proj_w, wph, wpl, DIM,  DIM);
    wconvert<<<dim3(MLPD / 32,    DIM / 32, DEPTH), blk>>>(mlp_w1, w1h, w1l, DIM,  MLPD);
    wconvert<<<dim3(DIM / 32,    MLPD / 32, DEPTH), blk>>>(mlp_w2, w2h, w2l, MLPD, DIM);

    const int nx = TOK * DIM;
    copy_kernel<<<(nx + 255) / 256, 256>>>(x_in, px, nx);

    for (int l = 0; l < DEPTH; l++) {
        size_t oq = (size_t)l * 3 * DIM * DIM;
        size_t op = (size_t)l * DIM * DIM;
        size_t o1 = (size_t)l * MLPD * DIM;
        size_t o2 = (size_t)l * DIM * MLPD;

        // ---- attention sublayer ----
        ln_split<<<TOK, 256>>>(px, ln1_w + (size_t)l * DIM, ln1_b + (size_t)l * DIM, pyh, pyl);
        gemm_mma<1><<<dim3(3 * DIM / 128, TOK / 128), 256, SMEMSZ>>>(
            pyh, pyl, wqh + oq, wql + oq, qkv_b + (size_t)l * 3 * DIM, nullptr,
            pqkv, nullptr, nullptr, TOK, 3 * DIM, DIM);
        qk_kernel<<<dim3(16, 16, BATCH * HEADS), 256>>>(pqkv, pS);
        softmax_kernel<<<BATCH * HEADS * SEQ, 256>>>(pS);
        sv_kernel<<<dim3(16, BATCH * HEADS), 256>>>(pS, pqkv, pah, pal);
        gemm_mma<3><<<dim3(DIM / 128, TOK / 128), 256, SMEMSZ>>>(
            pah, pal, wph + op, wpl + op, proj_b + (size_t)l * DIM, px,
            px, nullptr, nullptr, TOK, DIM, DIM);

        // ---- MLP sublayer ----
        ln_split<<<TOK, 256>>>(px, ln2_w + (size_t)l * DIM, ln2_b + (size_t)l * DIM, pyh, pyl);
        gemm_mma<2><<<dim3(MLPD / 128, TOK / 128), 256, SMEMSZ>>>(
            pyh, pyl, w1h + o1, w1l + o1, mlp_b1 + (size_t)l * MLPD, nullptr,
            nullptr, phh, phl, TOK, MLPD, DIM);
        gemm_mma<3><<<dim3(DIM / 128, TOK / 128), 256, SMEMSZ>>>(
            phh, phl, w2h + o2, w2l + o2, mlp_b2 + (size_t)l * DIM, px,
            px, nullptr, nullptr, TOK, DIM, MLPD);
    }

    copy_kernel<<<(nx + 255) / 256, 256>>>(px, out, nx);
}

// round 4
// speedup vs baseline: 2.4409x; 1.4700x over previous
#include <cuda_runtime.h>
#include <cuda_bf16.h>
#include <math.h>
#include <stdint.h>

// ----------------------------------------------------------------------------
// Transformer forward: 6 layers, B=4, N=1024, D=1024, H=16, hd=64, MLP=4096
// Round 3: dense GEMMs on mma.sync bf16x3 + fused flash attention (HMMA).
// ----------------------------------------------------------------------------

static constexpr int BATCH  = 4;
static constexpr int SEQ    = 1024;
static constexpr int DIM    = 1024;
static constexpr int HEADS  = 16;
static constexpr int HD     = 64;
static constexpr int MLPD   = 4096;
static constexpr int DEPTH  = 6;
static constexpr int TOK    = BATCH * SEQ;          // 4096
static constexpr float EPS  = 1e-5f;
static constexpr float SCALE = 0.03125f;            // DIM^-0.5

// ---------------- scratch (device globals; no allocation) -------------------
__device__ float         g_x   [(size_t)TOK * DIM];
__device__ __nv_bfloat16 g_yh  [(size_t)TOK * DIM];
__device__ __nv_bfloat16 g_yl  [(size_t)TOK * DIM];
__device__ __nv_bfloat16 g_qh  [(size_t)TOK * DIM];   // [bh][n][64] layouts
__device__ __nv_bfloat16 g_ql  [(size_t)TOK * DIM];
__device__ __nv_bfloat16 g_kh  [(size_t)TOK * DIM];
__device__ __nv_bfloat16 g_kl  [(size_t)TOK * DIM];
__device__ __nv_bfloat16 g_vh  [(size_t)TOK * DIM];
__device__ __nv_bfloat16 g_vl  [(size_t)TOK * DIM];
__device__ __nv_bfloat16 g_ah  [(size_t)TOK * DIM];   // attn out [tok][DIM]
__device__ __nv_bfloat16 g_al  [(size_t)TOK * DIM];
__device__ __nv_bfloat16 g_hh  [(size_t)TOK * MLPD];
__device__ __nv_bfloat16 g_hl  [(size_t)TOK * MLPD];

// transposed + hi/lo-split weights (written per launch; deterministic)
__device__ __nv_bfloat16 g_wq_h[(size_t)DEPTH * 3 * DIM * DIM];
__device__ __nv_bfloat16 g_wq_l[(size_t)DEPTH * 3 * DIM * DIM];
__device__ __nv_bfloat16 g_wp_h[(size_t)DEPTH * DIM * DIM];
__device__ __nv_bfloat16 g_wp_l[(size_t)DEPTH * DIM * DIM];
__device__ __nv_bfloat16 g_w1_h[(size_t)DEPTH * MLPD * DIM];
__device__ __nv_bfloat16 g_w1_l[(size_t)DEPTH * MLPD * DIM];
__device__ __nv_bfloat16 g_w2_h[(size_t)DEPTH * DIM * MLPD];
__device__ __nv_bfloat16 g_w2_l[(size_t)DEPTH * DIM * MLPD];

// ---------------------------- PTX helpers -----------------------------------
__device__ __forceinline__ uint32_t smem_u32(const void* p) {
    uint32_t a;
    asm("{ .reg .u64 t; cvta.to.shared.u64 t, %1; cvt.u32.u64 %0, t; }"
        : "=r"(a) : "l"(p));
    return a;
}

__device__ __forceinline__ void ldsm4(uint32_t* r, uint32_t a) {
    asm volatile("ldmatrix.sync.aligned.m8n8.x4.shared.b16 {%0,%1,%2,%3}, [%4];"
        : "=r"(r[0]), "=r"(r[1]), "=r"(r[2]), "=r"(r[3]) : "r"(a));
}
__device__ __forceinline__ void ldsm4t(uint32_t* r, uint32_t a) {
    asm volatile("ldmatrix.sync.aligned.m8n8.x4.trans.shared.b16 {%0,%1,%2,%3}, [%4];"
        : "=r"(r[0]), "=r"(r[1]), "=r"(r[2]), "=r"(r[3]) : "r"(a));
}

__device__ __forceinline__ void mma16816(float* c, const uint32_t* a,
                                         uint32_t b0, uint32_t b1) {
    asm volatile("mma.sync.aligned.m16n8k16.row.col.f32.bf16.bf16.f32 "
        "{%0,%1,%2,%3}, {%4,%5,%6,%7}, {%8,%9}, {%0,%1,%2,%3};"
        : "+f"(c[0]), "+f"(c[1]), "+f"(c[2]), "+f"(c[3])
        : "r"(a[0]), "r"(a[1]), "r"(a[2]), "r"(a[3]), "r"(b0), "r"(b1));
}

#define CP_ASYNC16(saddr, gptr) \
    asm volatile("cp.async.cg.shared.global [%0], [%1], 16;" :: "r"(saddr), "l"(gptr))
#define CP_COMMIT() asm volatile("cp.async.commit_group;" ::: "memory")
#define CP_WAIT(n)  asm volatile("cp.async.wait_group %0;" :: "n"(n) : "memory")

__device__ __forceinline__ uint32_t packbf2(float x, float y) {
    __nv_bfloat162 p = __floats2bfloat162_rn(x, y);
    return *(uint32_t*)&p;
}

// ----------------------------------------------------------------------------
__global__ void copy_kernel(const float* __restrict__ in, float* __restrict__ out, int n) {
    int i = blockIdx.x * blockDim.x + threadIdx.x;
    if (i < n) out[i] = in[i];
}

// ----------------------------------------------------------------------------
// Weight transpose + hi/lo split: W [L,K,N] fp32 -> Wt_hi/lo [L,N,K] bf16
__global__ void wconvert(const float* __restrict__ W, __nv_bfloat16* __restrict__ Th,
                         __nv_bfloat16* __restrict__ Tl, int K, int N) {
    __shared__ float t[32][33];
    size_t loff = (size_t)blockIdx.z * K * N;
    const float* Wl = W + loff;
    int n0 = blockIdx.x * 32, k0 = blockIdx.y * 32;
    #pragma unroll
    for (int i = 0; i < 4; i++) {
        int k = k0 + threadIdx.y + i * 8;
        t[threadIdx.y + i * 8][threadIdx.x] = Wl[(size_t)k * N + n0 + threadIdx.x];
    }
    __syncthreads();
    #pragma unroll
    for (int i = 0; i < 4; i++) {
        int n = n0 + threadIdx.y + i * 8;
        float v = t[threadIdx.x][threadIdx.y + i * 8];
        __nv_bfloat16 h = __float2bfloat16(v);
        float lo = v - __bfloat162float(h);
        size_t o = loff + (size_t)n * K + k0 + threadIdx.x;
        Th[o] = h;
        Tl[o] = __float2bfloat16(lo);
    }
}

// ----------------------------------------------------------------------------
// LayerNorm with hi/lo bf16 split output
__global__ void ln_split(const float* __restrict__ x,
                         const float* __restrict__ w,
                         const float* __restrict__ b,
                         __nv_bfloat16* __restrict__ yh,
                         __nv_bfloat16* __restrict__ yl) {
    int row = blockIdx.x;
    const float* xr = x + (size_t)row * DIM;
    __shared__ float red[256];
    int t = threadIdx.x;

    float s = 0.f;
    for (int i = t; i < DIM; i += 256) s += xr[i];
    red[t] = s; __syncthreads();
    for (int o = 128; o > 0; o >>= 1) { if (t < o) red[t] += red[t + o]; __syncthreads(); }
    float mu = red[0] * (1.0f / DIM);
    __syncthreads();

    float v = 0.f;
    for (int i = t; i < DIM; i += 256) { float d = xr[i] - mu; v += d * d; }
    red[t] = v; __syncthreads();
    for (int o = 128; o > 0; o >>= 1) { if (t < o) red[t] += red[t + o]; __syncthreads(); }
    float rstd = rsqrtf(red[0] * (1.0f / DIM) + EPS);

    for (int i = t; i < DIM; i += 256) {
        float y = (xr[i] - mu) * rstd * w[i] + b[i];
        __nv_bfloat16 h = __float2bfloat16(y);
        yh[(size_t)row * DIM + i] = h;
        yl[(size_t)row * DIM + i] = __float2bfloat16(y - __bfloat162float(h));
    }
}

// ----------------------------------------------------------------------------
// Tensor-core GEMM via mma.sync bf16 (bf16x3): C[M,N] = A[M,K] @ W[K,N]
// EPI: 2 = +bias,gelu -> bf16 hi/lo;  3 = +bias+res -> fp32 Cf;
//      4 = +bias -> scatter hi/lo bf16 Q/K/V to per-head [bh][n][64] layout
template<int EPI>
__global__ void __launch_bounds__(256, 1)
gemm_mma(const __nv_bfloat16* __restrict__ Ah, const __nv_bfloat16* __restrict__ Al,
         const __nv_bfloat16* __restrict__ Bh, const __nv_bfloat16* __restrict__ Bl,
         const float* __restrict__ bias, const float* __restrict__ res,
         float* __restrict__ Cf, __nv_bfloat16* __restrict__ Ch,
         __nv_bfloat16* __restrict__ Cl,
         __nv_bfloat16* __restrict__ Qh, __nv_bfloat16* __restrict__ Qlo,
         __nv_bfloat16* __restrict__ Kh, __nv_bfloat16* __restrict__ Klo,
         __nv_bfloat16* __restrict__ Vh, __nv_bfloat16* __restrict__ Vlo,
         int M, int N, int K) {
    constexpr int STAGES = 3;
    constexpr int ROWB   = 80;            // padded row stride (bytes) for 32 bf16
    constexpr int TILEB  = 128 * ROWB;    // 10240 B per operand tile
    constexpr int STAGEB = 4 * TILEB;     // 40960 B per stage

    extern __shared__ char smem[];
    uint32_t sb = smem_u32(smem);
    int tid = threadIdx.x, lane = tid & 31, wid = tid >> 5;
    int bm = blockIdx.y * 128, bn = blockIdx.x * 128;
    int warp_m = wid >> 2, warp_n = wid & 3;

    const __nv_bfloat16* srcs[4] = { Ah + (size_t)bm * K, Al + (size_t)bm * K,
                                     Bh + (size_t)bn * K, Bl + (size_t)bn * K };
    int nch = K >> 5;

    int g = lane >> 3;
    uint32_t rowsel = (uint32_t)(((g & 1) << 3) + (lane & 7));
    uint32_t colsel = (uint32_t)((g >> 1) * 16);

    float acc[4][4][4];
    #pragma unroll
    for (int i = 0; i < 4; i++)
        #pragma unroll
        for (int j = 0; j < 4; j++)
            #pragma unroll
            for (int q = 0; q < 4; q++) acc[i][j][q] = 0.f;

    auto issue = [&](int ch) {
        int k0 = ch << 5;
        uint32_t sbase = sb + (uint32_t)(ch % STAGES) * STAGEB;
        #pragma unroll
        for (int j = 0; j < 8; j++) {
            int c2 = j * 256 + tid;
            int op = c2 >> 9, idx = c2 & 511, row = idx >> 2, ck = idx & 3;
            const __nv_bfloat16* gp = srcs[op] + (size_t)row * K + k0 + ck * 8;
            uint32_t sa = sbase + (uint32_t)(op * TILEB + row * ROWB + ck * 16);
            CP_ASYNC16(sa, gp);
        }
    };

    #pragma unroll
    for (int s = 0; s < STAGES; s++) { issue(s); CP_COMMIT(); }

    for (int c = 0; c < nch; c++) {
        CP_WAIT(STAGES - 1);
        __syncthreads();
        uint32_t st = sb + (uint32_t)((c % STAGES) * STAGEB);

        #pragma unroll
        for (int kh2 = 0; kh2 < 2; kh2++) {
            uint32_t kb = (uint32_t)(kh2 * 32) + colsel;
            uint32_t ah[4][4], al[4][4], bh[2][4], bl[2][4];
            #pragma unroll
            for (int mi = 0; mi < 4; mi++) {
                uint32_t r = (uint32_t)(warp_m * 64 + mi * 16) + rowsel;
                ldsm4(ah[mi], st + r * ROWB + kb);
                ldsm4(al[mi], st + TILEB + r * ROWB + kb);
            }
            #pragma unroll
            for (int ni = 0; ni < 2; ni++) {
                uint32_t r = (uint32_t)(warp_n * 32 + ni * 16) + rowsel;
                ldsm4(bh[ni], st + 2 * TILEB + r * ROWB + kb);
                ldsm4(bl[ni], st + 3 * TILEB + r * ROWB + kb);
            }
            #pragma unroll
            for (int mi = 0; mi < 4; mi++)
                #pragma unroll
                for (int nj = 0; nj < 4; nj++)
                    mma16816(acc[mi][nj], ah[mi], bh[nj >> 1][nj & 1], bh[nj >> 1][(nj & 1) + 2]);
            #pragma unroll
            for (int mi = 0; mi < 4; mi++)
                #pragma unroll
                for (int nj = 0; nj < 4; nj++)
                    mma16816(acc[mi][nj], ah[mi], bl[nj >> 1][nj & 1], bl[nj >> 1][(nj & 1) + 2]);
            #pragma unroll
            for (int mi = 0; mi < 4; mi++)
                #pragma unroll
                for (int nj = 0; nj < 4; nj++)
                    mma16816(acc[mi][nj], al[mi], bh[nj >> 1][nj & 1], bh[nj >> 1][(nj & 1) + 2]);
        }
        __syncthreads();
        if (c + STAGES < nch) issue(c + STAGES);
        CP_COMMIT();
    }

    // ---- epilogue ----
    #pragma unroll
    for (int mi = 0; mi < 4; mi++) {
        int r0 = bm + warp_m * 64 + mi * 16 + (lane >> 2);
        #pragma unroll
        for (int nj = 0; nj < 4; nj++) {
            int cc = bn + warp_n * 32 + nj * 8 + (lane & 3) * 2;
            float b0 = bias[cc], b1 = bias[cc + 1];
            #pragma unroll
            for (int half = 0; half < 2; half++) {
                int r = r0 + half * 8;
                float v0 = acc[mi][nj][half * 2 + 0] + b0;
                float v1 = acc[mi][nj][half * 2 + 1] + b1;
                if (EPI == 2) {
                    size_t o = (size_t)r * N + cc;
                    v0 = 0.5f * v0 * (1.0f + erff(v0 * 0.70710678118654752f));
                    v1 = 0.5f * v1 * (1.0f + erff(v1 * 0.70710678118654752f));
                    __nv_bfloat16 h0 = __float2bfloat16(v0);
                    __nv_bfloat16 h1 = __float2bfloat16(v1);
                    *(uint32_t*)(Ch + o) = packbf2(v0, v1);
                    *(uint32_t*)(Cl + o) = packbf2(v0 - __bfloat162float(h0),
                                                   v1 - __bfloat162float(h1));
                } else if (EPI == 3) {
                    size_t o = (size_t)r * N + cc;
                    v0 += res[o];
                    v1 += res[o + 1];
                    float2 f2; f2.x = v0; f2.y = v1;
                    *(float2*)(Cf + o) = f2;
                } else {  // EPI == 4: scatter qkv -> per-head layout
                    int sel = cc >> 10, hh = (cc >> 6) & 15, d = cc & 63;
                    int bb = r >> 10, nn = r & 1023;
                    size_t o = ((size_t)((bb << 4) + hh) * SEQ + nn) * 64 + d;
                    __nv_bfloat16* dh = (sel == 0) ? Qh : (sel == 1) ? Kh : Vh;
                    __nv_bfloat16* dl = (sel == 0) ? Qlo : (sel == 1) ? Klo : Vlo;
                    __nv_bfloat16 h0 = __float2bfloat16(v0);
                    __nv_bfloat16 h1 = __float2bfloat16(v1);
                    *(uint32_t*)(dh + o) = packbf2(v0, v1);
                    *(uint32_t*)(dl + o) = packbf2(v0 - __bfloat162float(h0),
                                                   v1 - __bfloat162float(h1));
                }
            }
        }
    }
}

// ----------------------------------------------------------------------------
// Fused flash attention: per CTA, one (b,h) and 128 Q rows; loops 16 KV tiles
// of 64 keys. QK^T and P.V on HMMA with hi/lo compensation; online softmax.
// Output: hi/lo bf16 at [tok][DIM] (col = h*64+d) feeding the proj GEMM.
__global__ void __launch_bounds__(256, 1)
flash_kernel(const __nv_bfloat16* __restrict__ Qh, const __nv_bfloat16* __restrict__ Ql,
             const __nv_bfloat16* __restrict__ Kh, const __nv_bfloat16* __restrict__ Kl,
             const __nv_bfloat16* __restrict__ Vh, const __nv_bfloat16* __restrict__ Vl,
             __nv_bfloat16* __restrict__ Oh, __nv_bfloat16* __restrict__ Ol) {
    constexpr int RSTR  = 144;            // padded row stride bytes (64 bf16 + 16B)
    constexpr int KVT   = 64 * RSTR;      // 9216 B per KV operand tile
    constexpr int STAGEB = 4 * KVT;       // 36864 B per stage
    constexpr int QB    = 128 * RSTR;     // 18432 B per Q operand

    extern __shared__ char smem[];
    uint32_t sb = smem_u32(smem);
    int tid = threadIdx.x, lane = tid & 31, wid = tid >> 5;
    int bh = blockIdx.y, i0 = blockIdx.x * 128;
    size_t seqb = (size_t)bh * SEQ * 64;

    // --- Q load (cp.async) ---
    {
        const __nv_bfloat16* qs[2] = { Qh + seqb + (size_t)i0 * 64,
                                       Ql + seqb + (size_t)i0 * 64 };
        #pragma unroll
        for (int j = 0; j < 8; j++) {
            int idx = j * 256 + tid;
            int op = idx >> 10, rem = idx & 1023, row = rem >> 3, ck = rem & 7;
            CP_ASYNC16(sb + (uint32_t)(op * QB + row * RSTR + ck * 16),
                       qs[op] + (size_t)row * 64 + ck * 8);
        }
        CP_COMMIT();
    }
    const __nv_bfloat16* kvs[4] = { Kh + seqb, Kl + seqb, Vh + seqb, Vl + seqb };
    auto issueKV = [&](int it) {
        int k0 = it * 64;
        uint32_t base = sb + 2 * QB + (uint32_t)(it & 1) * STAGEB;
        #pragma unroll
        for (int j = 0; j < 8; j++) {
            int idx = j * 256 + tid;
            int op = idx >> 9, rem = idx & 511, row = rem >> 3, ck = rem & 7;
            CP_ASYNC16(base + (uint32_t)(op * KVT + row * RSTR + ck * 16),
                       kvs[op] + (size_t)(k0 + row) * 64 + ck * 8);
        }
    };
    issueKV(0); CP_COMMIT();
    issueKV(1); CP_COMMIT();

    int g = lane >> 3;
    uint32_t lrow = (uint32_t)(((g & 1) << 3) + (lane & 7));
    uint32_t lcol = (uint32_t)((g >> 1) * 16);

    // --- Q fragments (held in registers) ---
    CP_WAIT(2);
    __syncthreads();
    uint32_t qfh[4][4], qfl[4][4];
    {
        int r0 = wid * 16;
        #pragma unroll
        for (int c = 0; c < 4; c++) {
            ldsm4(qfh[c], sb + (uint32_t)((r0 + lrow) * RSTR + c * 32) + lcol);
            ldsm4(qfl[c], sb + QB + (uint32_t)((r0 + lrow) * RSTR + c * 32) + lcol);
        }
    }

    float m0 = -1e30f, m1 = -1e30f, l0 = 0.f, l1 = 0.f;
    float o[8][4];
    #pragma unroll
    for (int nb = 0; nb < 8; nb++)
        #pragma unroll
        for (int q = 0; q < 4; q++) o[nb][q] = 0.f;

    for (int it = 0; it < 16; it++) {
        CP_WAIT(1);
        __syncthreads();
        uint32_t st = sb + 2 * QB + (uint32_t)(it & 1) * STAGEB;

        // ---- S = (Q K^T) ----
        float s[8][4];
        #pragma unroll
        for (int nb = 0; nb < 8; nb++)
            #pragma unroll
            for (int q = 0; q < 4; q++) s[nb][q] = 0.f;

        #pragma unroll
        for (int c = 0; c < 4; c++) {
            uint32_t kfh[4][4], kfl[4][4];
            #pragma unroll
            for (int p = 0; p < 4; p++) {
                uint32_t a = st + (uint32_t)((p * 16 + lrow) * RSTR + c * 32) + lcol;
                ldsm4(kfh[p], a);
                ldsm4(kfl[p], a + KVT);
            }
            #pragma unroll
            for (int p = 0; p < 4; p++) {
                mma16816(s[2 * p],     qfh[c], kfh[p][0], kfh[p][2]);
                mma16816(s[2 * p + 1], qfh[c], kfh[p][1], kfh[p][3]);
                mma16816(s[2 * p],     qfh[c], kfl[p][0], kfl[p][2]);
                mma16816(s[2 * p + 1], qfh[c], kfl[p][1], kfl[p][3]);
                mma16816(s[2 * p],     qfl[c], kfh[p][0], kfh[p][2]);
                mma16816(s[2 * p + 1], qfl[c], kfh[p][1], kfh[p][3]);
            }
        }

        // ---- online softmax ----
        float rm0 = -1e30f, rm1 = -1e30f;
        #pragma unroll
        for (int nb = 0; nb < 8; nb++) {
            #pragma unroll
            for (int q = 0; q < 4; q++) s[nb][q] *= SCALE;
            rm0 = fmaxf(rm0, fmaxf(s[nb][0], s[nb][1]));
            rm1 = fmaxf(rm1, fmaxf(s[nb][2], s[nb][3]));
        }
        rm0 = fmaxf(rm0, __shfl_xor_sync(0xffffffffu, rm0, 1));
        rm0 = fmaxf(rm0, __shfl_xor_sync(0xffffffffu, rm0, 2));
        rm1 = fmaxf(rm1, __shfl_xor_sync(0xffffffffu, rm1, 1));
        rm1 = fmaxf(rm1, __shfl_xor_sync(0xffffffffu, rm1, 2));
        float nm0 = fmaxf(m0, rm0), nm1 = fmaxf(m1, rm1);
        float a0 = __expf(m0 - nm0), a1 = __expf(m1 - nm1);
        m0 = nm0; m1 = nm1;

        float sum0 = 0.f, sum1 = 0.f;
        uint32_t pfh[4][4], pfl[4][4];
        #pragma unroll
        for (int nb = 0; nb < 8; nb++) {
            float p00 = __expf(s[nb][0] - nm0);
            float p01 = __expf(s[nb][1] - nm0);
            float p10 = __expf(s[nb][2] - nm1);
            float p11 = __expf(s[nb][3] - nm1);
            sum0 += p00 + p01;
            sum1 += p10 + p11;
            float h00 = __bfloat162float(__float2bfloat16(p00));
            float h01 = __bfloat162float(__float2bfloat16(p01));
            float h10 = __bfloat162float(__float2bfloat16(p10));
            float h11 = __bfloat162float(__float2bfloat16(p11));
            int c = nb >> 1, off = (nb & 1) ? 2 : 0;
            pfh[c][off + 0] = packbf2(h00, h01);
            pfh[c][off + 1] = packbf2(h10, h11);
            pfl[c][off + 0] = packbf2(p00 - h00, p01 - h01);
            pfl[c][off + 1] = packbf2(p10 - h10, p11 - h11);
        }
        sum0 += __shfl_xor_sync(0xffffffffu, sum0, 1);
        sum0 += __shfl_xor_sync(0xffffffffu, sum0, 2);
        sum1 += __shfl_xor_sync(0xffffffffu, sum1, 1);
        sum1 += __shfl_xor_sync(0xffffffffu, sum1, 2);
        l0 = l0 * a0 + sum0;
        l1 = l1 * a1 + sum1;
        #pragma unroll
        for (int nb = 0; nb < 8; nb++) {
            o[nb][0] *= a0; o[nb][1] *= a0;
            o[nb][2] *= a1; o[nb][3] *= a1;
        }

        // ---- O += P V ----
        #pragma unroll
        for (int c = 0; c < 4; c++) {
            uint32_t vfh[4][4], vfl[4][4];
            #pragma unroll
            for (int dp = 0; dp < 4; dp++) {
                uint32_t a = st + 2 * KVT + (uint32_t)((c * 16 + lrow) * RSTR + dp * 32) + lcol;
                ldsm4t(vfh[dp], a);
                ldsm4t(vfl[dp], a + KVT);
            }
            #pragma unroll
            for (int dp = 0; dp < 4; dp++) {
                mma16816(o[2 * dp],     pfh[c], vfh[dp][0], vfh[dp][1]);
                mma16816(o[2 * dp + 1], pfh[c], vfh[dp][2], vfh[dp][3]);
                mma16816(o[2 * dp],     pfh[c], vfl[dp][0], vfl[dp][1]);
                mma16816(o[2 * dp + 1], pfh[c], vfl[dp][2], vfl[dp][3]);
                mma16816(o[2 * dp],     pfl[c], vfh[dp][0], vfh[dp][1]);
                mma16816(o[2 * dp + 1], pfl[c], vfh[dp][2], vfh[dp][3]);
            }
        }
        __syncthreads();
        if (it + 2 < 16) issueKV(it + 2);
        CP_COMMIT();
    }

    // ---- epilogue ----
    float inv0 = 1.0f / l0, inv1 = 1.0f / l1;
    int b = bh >> 4, h = bh & 15;
    int nrow = i0 + wid * 16 + (lane >> 2);
    size_t t0 = (size_t)b * SEQ + nrow;
    #pragma unroll
    for (int nb = 0; nb < 8; nb++) {
        int col = h * 64 + nb * 8 + (lane & 3) * 2;
        float v0 = o[nb][0] * inv0, v1 = o[nb][1] * inv0;
        float v2 = o[nb][2] * inv1, v3 = o[nb][3] * inv1;
        float h0 = __bfloat162float(__float2bfloat16(v0));
        float h1 = __bfloat162float(__float2bfloat16(v1));
        float h2 = __bfloat162float(__float2bfloat16(v2));
        float h3 = __bfloat162float(__float2bfloat16(v3));
        *(uint32_t*)(Oh + t0 * DIM + col) = packbf2(v0, v1);
        *(uint32_t*)(Ol + t0 * DIM + col) = packbf2(v0 - h0, v1 - h1);
        *(uint32_t*)(Oh + (t0 + 8) * DIM + col) = packbf2(v2, v3);
        *(uint32_t*)(Ol + (t0 + 8) * DIM + col) = packbf2(v2 - h2, v3 - h3);
    }
}

// ----------------------------------------------------------------------------
extern "C" void kernel_launch(void* const* d_in, const int* in_sizes, int n_in,
                              void* d_out, int out_size) {
    const float* x_in   = (const float*)d_in[0];
    const float* ln1_w  = (const float*)d_in[1];
    const float* ln1_b  = (const float*)d_in[2];
    const float* qkv_w  = (const float*)d_in[3];
    const float* qkv_b  = (const float*)d_in[4];
    const float* proj_w = (const float*)d_in[5];
    const float* proj_b = (const float*)d_in[6];
    const float* ln2_w  = (const float*)d_in[7];
    const float* ln2_b  = (const float*)d_in[8];
    const float* mlp_w1 = (const float*)d_in[9];
    const float* mlp_b1 = (const float*)d_in[10];
    const float* mlp_w2 = (const float*)d_in[11];
    const float* mlp_b2 = (const float*)d_in[12];
    float* out = (float*)d_out;

    float *px;
    __nv_bfloat16 *pyh, *pyl, *pqh, *pql, *pkh, *pkl, *pvh, *pvl, *pah, *pal, *phh, *phl;
    __nv_bfloat16 *wqh, *wql, *wph, *wpl, *w1h, *w1l, *w2h, *w2l;
    cudaGetSymbolAddress((void**)&px,   g_x);
    cudaGetSymbolAddress((void**)&pyh,  g_yh);
    cudaGetSymbolAddress((void**)&pyl,  g_yl);
    cudaGetSymbolAddress((void**)&pqh,  g_qh);
    cudaGetSymbolAddress((void**)&pql,  g_ql);
    cudaGetSymbolAddress((void**)&pkh,  g_kh);
    cudaGetSymbolAddress((void**)&pkl,  g_kl);
    cudaGetSymbolAddress((void**)&pvh,  g_vh);
    cudaGetSymbolAddress((void**)&pvl,  g_vl);
    cudaGetSymbolAddress((void**)&pah,  g_ah);
    cudaGetSymbolAddress((void**)&pal,  g_al);
    cudaGetSymbolAddress((void**)&phh,  g_hh);
    cudaGetSymbolAddress((void**)&phl,  g_hl);
    cudaGetSymbolAddress((void**)&wqh,  g_wq_h);
    cudaGetSymbolAddress((void**)&wql,  g_wq_l);
    cudaGetSymbolAddress((void**)&wph,  g_wp_h);
    cudaGetSymbolAddress((void**)&wpl,  g_wp_l);
    cudaGetSymbolAddress((void**)&w1h,  g_w1_h);
    cudaGetSymbolAddress((void**)&w1l,  g_w1_l);
    cudaGetSymbolAddress((void**)&w2h,  g_w2_h);
    cudaGetSymbolAddress((void**)&w2l,  g_w2_l);

    const int SMEMSZ  = 3 * 4 * 128 * 80;                  // 122880 B (gemm)
    const int FSMEMSZ = 2 * 128 * 144 + 2 * 4 * 64 * 144;  // 110592 B (flash)
    cudaFuncSetAttribute(gemm_mma<2>, cudaFuncAttributeMaxDynamicSharedMemorySize, SMEMSZ);
    cudaFuncSetAttribute(gemm_mma<3>, cudaFuncAttributeMaxDynamicSharedMemorySize, SMEMSZ);
    cudaFuncSetAttribute(gemm_mma<4>, cudaFuncAttributeMaxDynamicSharedMemorySize, SMEMSZ);
    cudaFuncSetAttribute(flash_kernel, cudaFuncAttributeMaxDynamicSharedMemorySize, FSMEMSZ);

    // weight transpose + split
    dim3 blk(32, 8);
    wconvert<<<dim3(3 * DIM / 32, DIM / 32, DEPTH), blk>>>(qkv_w,  wqh, wql, DIM,  3 * DIM);
    wconvert<<<dim3(DIM / 32,     DIM / 32, DEPTH), blk>>>(proj_w, wph, wpl, DIM,  DIM);
    wconvert<<<dim3(MLPD / 32,    DIM / 32, DEPTH), blk>>>(mlp_w1, w1h, w1l, DIM,  MLPD);
    wconvert<<<dim3(DIM / 32,    MLPD / 32, DEPTH), blk>>>(mlp_w2, w2h, w2l, MLPD, DIM);

    const int nx = TOK * DIM;
    copy_kernel<<<(nx + 255) / 256, 256>>>(x_in, px, nx);

    for (int l = 0; l < DEPTH; l++) {
        size_t oq = (size_t)l * 3 * DIM * DIM;
        size_t op = (size_t)l * DIM * DIM;
        size_t o1 = (size_t)l * MLPD * DIM;
        size_t o2 = (size_t)l * DIM * MLPD;

        // ---- attention sublayer ----
        ln_split<<<TOK, 256>>>(px, ln1_w + (size_t)l * DIM, ln1_b + (size_t)l * DIM, pyh, pyl);
        gemm_mma<4><<<dim3(3 * DIM / 128, TOK / 128), 256, SMEMSZ>>>(
            pyh, pyl, wqh + oq, wql + oq, qkv_b + (size_t)l * 3 * DIM, nullptr,
            nullptr, nullptr, nullptr,
            pqh, pql, pkh, pkl, pvh, pvl, TOK, 3 * DIM, DIM);
        flash_kernel<<<dim3(8, BATCH * HEADS), 256, FSMEMSZ>>>(
            pqh, pql, pkh, pkl, pvh, pvl, pah, pal);
        gemm_mma<3><<<dim3(DIM / 128, TOK / 128), 256, SMEMSZ>>>(
            pah, pal, wph + op, wpl + op, proj_b + (size_t)l * DIM, px,
            px, nullptr, nullptr,
            nullptr, nullptr, nullptr, nullptr, nullptr, nullptr, TOK, DIM, DIM);

        // ---- MLP sublayer ----
        ln_split<<<TOK, 256>>>(px, ln2_w + (size_t)l * DIM, ln2_b + (size_t)l * DIM, pyh, pyl);
        gemm_mma<2><<<dim3(MLPD / 128, TOK / 128), 256, SMEMSZ>>>(
            pyh, pyl, w1h + o1, w1l + o1, mlp_b1 + (size_t)l * MLPD, nullptr,
            nullptr, phh, phl,
            nullptr, nullptr, nullptr, nullptr, nullptr, nullptr, TOK, MLPD, DIM);
        gemm_mma<3><<<dim3(DIM / 128, TOK / 128), 256, SMEMSZ>>>(
            phh, phl, w2h + o2, w2l + o2, mlp_b2 + (size_t)l * DIM, px,
            px, nullptr, nullptr,
            nullptr, nullptr, nullptr, nullptr, nullptr, nullptr, TOK, DIM, MLPD);
    }

    copy_kernel<<<(nx + 255) / 256, 256>>>(px, out, nx);
}

// round 7
// speedup vs baseline: 3.3732x; 1.3820x over previous
#include <cuda_runtime.h>
#include <cuda_bf16.h>
#include <cuda_fp16.h>
#include <math.h>
#include <stdint.h>

// ----------------------------------------------------------------------------
// Transformer forward: 6 layers, B=4, N=1024, D=1024, H=16, hd=64, MLP=4096
// Round 5: dense GEMMs fp16 2-product (weight hi/lo split, dual accumulator);
// flash attention unchanged (bf16x3). LN rewritten warp-per-row one-pass.
// ----------------------------------------------------------------------------

static constexpr int BATCH  = 4;
static constexpr int SEQ    = 1024;
static constexpr int DIM    = 1024;
static constexpr int HEADS  = 16;
static constexpr int HD     = 64;
static constexpr int MLPD   = 4096;
static constexpr int DEPTH  = 6;
static constexpr int TOK    = BATCH * SEQ;          // 4096
static constexpr float EPS  = 1e-5f;
static constexpr float SCALE = 0.03125f;            // DIM^-0.5
static constexpr float INV2048 = 1.0f / 2048.0f;

// ---------------- scratch (device globals; no allocation) -------------------
__device__ float         g_x   [(size_t)TOK * DIM];
__device__ __half        g_y   [(size_t)TOK * DIM];   // LN out, fp16
__device__ __nv_bfloat16 g_qh  [(size_t)TOK * DIM];   // [bh][n][64] layouts
__device__ __nv_bfloat16 g_ql  [(size_t)TOK * DIM];
__device__ __nv_bfloat16 g_kh  [(size_t)TOK * DIM];
__device__ __nv_bfloat16 g_kl  [(size_t)TOK * DIM];
__device__ __nv_bfloat16 g_vh  [(size_t)TOK * DIM];
__device__ __nv_bfloat16 g_vl  [(size_t)TOK * DIM];
__device__ __half        g_a   [(size_t)TOK * DIM];   // attn out, fp16
__device__ __half        g_h   [(size_t)TOK * MLPD];  // MLP hidden, fp16

// transposed + hi/lo-split fp16 weights (lo pre-scaled x2048)
__device__ __half g_wq_h[(size_t)DEPTH * 3 * DIM * DIM];
__device__ __half g_wq_l[(size_t)DEPTH * 3 * DIM * DIM];
__device__ __half g_wp_h[(size_t)DEPTH * DIM * DIM];
__device__ __half g_wp_l[(size_t)DEPTH * DIM * DIM];
__device__ __half g_w1_h[(size_t)DEPTH * MLPD * DIM];
__device__ __half g_w1_l[(size_t)DEPTH * MLPD * DIM];
__device__ __half g_w2_h[(size_t)DEPTH * DIM * MLPD];
__device__ __half g_w2_l[(size_t)DEPTH * DIM * MLPD];

// ---------------------------- PTX helpers -----------------------------------
__device__ __forceinline__ uint32_t smem_u32(const void* p) {
    uint32_t a;
    asm("{ .reg .u64 t; cvta.to.shared.u64 t, %1; cvt.u32.u64 %0, t; }"
        : "=r"(a) : "l"(p));
    return a;
}

__device__ __forceinline__ void ldsm4(uint32_t* r, uint32_t a) {
    asm volatile("ldmatrix.sync.aligned.m8n8.x4.shared.b16 {%0,%1,%2,%3}, [%4];"
        : "=r"(r[0]), "=r"(r[1]), "=r"(r[2]), "=r"(r[3]) : "r"(a));
}
__device__ __forceinline__ void ldsm4t(uint32_t* r, uint32_t a) {
    asm volatile("ldmatrix.sync.aligned.m8n8.x4.trans.shared.b16 {%0,%1,%2,%3}, [%4];"
        : "=r"(r[0]), "=r"(r[1]), "=r"(r[2]), "=r"(r[3]) : "r"(a));
}

// bf16 MMA (flash)
__device__ __forceinline__ void mma16816(float* c, const uint32_t* a,
                                         uint32_t b0, uint32_t b1) {
    asm volatile("mma.sync.aligned.m16n8k16.row.col.f32.bf16.bf16.f32 "
        "{%0,%1,%2,%3}, {%4,%5,%6,%7}, {%8,%9}, {%0,%1,%2,%3};"
        : "+f"(c[0]), "+f"(c[1]), "+f"(c[2]), "+f"(c[3])
        : "r"(a[0]), "r"(a[1]), "r"(a[2]), "r"(a[3]), "r"(b0), "r"(b1));
}
// fp16 MMA (dense GEMMs)
__device__ __forceinline__ void mma_h(float* c, const uint32_t* a,
                                      uint32_t b0, uint32_t b1) {
    asm volatile("mma.sync.aligned.m16n8k16.row.col.f32.f16.f16.f32 "
        "{%0,%1,%2,%3}, {%4,%5,%6,%7}, {%8,%9}, {%0,%1,%2,%3};"
        : "+f"(c[0]), "+f"(c[1]), "+f"(c[2]), "+f"(c[3])
        : "r"(a[0]), "r"(a[1]), "r"(a[2]), "r"(a[3]), "r"(b0), "r"(b1));
}

#define CP_ASYNC16(saddr, gptr) \
    asm volatile("cp.async.cg.shared.global [%0], [%1], 16;" :: "r"(saddr), "l"(gptr))
#define CP_COMMIT() asm volatile("cp.async.commit_group;" ::: "memory")
#define CP_WAIT(n)  asm volatile("cp.async.wait_group %0;" :: "n"(n) : "memory")

__device__ __forceinline__ uint32_t packbf2(float x, float y) {
    __nv_bfloat162 p = __floats2bfloat162_rn(x, y);
    return *(uint32_t*)&p;
}
__device__ __forceinline__ uint32_t packh2(float x, float y) {
    __half2 p = __floats2half2_rn(x, y);
    return *(uint32_t*)&p;
}

// ----------------------------------------------------------------------------
__global__ void copy_kernel(const float* __restrict__ in, float* __restrict__ out, int n) {
    int i = blockIdx.x * blockDim.x + threadIdx.x;
    if (i < n) out[i] = in[i];
}

// ----------------------------------------------------------------------------
// Weight transpose + fp16 hi/lo split: W [L,K,N] fp32 -> Wt [L,N,K] fp16
// lo = (w - hi) * 2048 (keeps it in fp16 normal range)
__global__ void wconvert(const float* __restrict__ W, __half* __restrict__ Th,
                         __half* __restrict__ Tl, int K, int N) {
    __shared__ float t[32][33];
    size_t loff = (size_t)blockIdx.z * K * N;
    const float* Wl = W + loff;
    int n0 = blockIdx.x * 32, k0 = blockIdx.y * 32;
    #pragma unroll
    for (int i = 0; i < 4; i++) {
        int k = k0 + threadIdx.y + i * 8;
        t[threadIdx.y + i * 8][threadIdx.x] = Wl[(size_t)k * N + n0 + threadIdx.x];
    }
    __syncthreads();
    #pragma unroll
    for (int i = 0; i < 4; i++) {
        int n = n0 + threadIdx.y + i * 8;
        float v = t[threadIdx.x][threadIdx.y + i * 8];
        __half h = __float2half_rn(v);
        float lo = (v - __half2float(h)) * 2048.0f;
        size_t o = loff + (size_t)n * K + k0 + threadIdx.x;
        Th[o] = h;
        Tl[o] = __float2half_rn(lo);
    }
}

// ----------------------------------------------------------------------------
// LayerNorm: warp per row, one pass (sum + sumsq), fp16 output.
// grid TOK/8, block 256.
__global__ void ln_half(const float* __restrict__ x,
                        const float* __restrict__ w,
                        const float* __restrict__ b,
                        __half* __restrict__ y) {
    int row = blockIdx.x * 8 + (threadIdx.x >> 5);
    int lane = threadIdx.x & 31;
    const float4* xr = (const float4*)(x + (size_t)row * DIM);
    const float4* w4 = (const float4*)w;
    const float4* b4 = (const float4*)b;

    float4 v[8];
    float s = 0.f, s2 = 0.f;
    #pragma unroll
    for (int i = 0; i < 8; i++) {
        v[i] = xr[lane + i * 32];
        s  += v[i].x + v[i].y + v[i].z + v[i].w;
        s2 += v[i].x * v[i].x + v[i].y * v[i].y + v[i].z * v[i].z + v[i].w * v[i].w;
    }
    #pragma unroll
    for (int o = 16; o > 0; o >>= 1) {
        s  += __shfl_xor_sync(0xffffffffu, s,  o);
        s2 += __shfl_xor_sync(0xffffffffu, s2, o);
    }
    float mu = s * (1.0f / DIM);
    float var = s2 * (1.0f / DIM) - mu * mu;
    float rstd = rsqrtf(var + EPS);

    __half* yr = y + (size_t)row * DIM;
    #pragma unroll
    for (int i = 0; i < 8; i++) {
        int idx = (lane + i * 32);
        float4 wv = w4[idx], bv = b4[idx];
        float g0 = (v[i].x - mu) * rstd * wv.x + bv.x;
        float g1 = (v[i].y - mu) * rstd * wv.y + bv.y;
        float g2 = (v[i].z - mu) * rstd * wv.z + bv.z;
        float g3 = (v[i].w - mu) * rstd * wv.w + bv.w;
        uint2 pk;
        pk.x = packh2(g0, g1);
        pk.y = packh2(g2, g3);
        *(uint2*)(yr + idx * 4) = pk;
    }
}

// ----------------------------------------------------------------------------
// Dense GEMM, fp16 2-product: C = A @ (Bh + Bl/2048)
// A fp16 [M,K]; Bh/Bl fp16 [N,K] (K-major, pre-transposed).
// acc1 += A*Bh ; acc2 += A*Bl ; C = acc1 + acc2/2048 + bias (+epilogue)
// EPI: 2 = gelu -> fp16 Ch;  3 = +res -> fp32 Cf;  4 = scatter bf16 hi/lo QKV
template<int EPI>
__global__ void __launch_bounds__(256, 1)
gemm_mma(const __half* __restrict__ A,
         const __half* __restrict__ Bh, const __half* __restrict__ Bl,
         const float* __restrict__ bias, const float* __restrict__ res,
         float* __restrict__ Cf, __half* __restrict__ Ch,
         __nv_bfloat16* __restrict__ Qh, __nv_bfloat16* __restrict__ Qlo,
         __nv_bfloat16* __restrict__ Kh, __nv_bfloat16* __restrict__ Klo,
         __nv_bfloat16* __restrict__ Vh, __nv_bfloat16* __restrict__ Vlo,
         int M, int N, int K) {
    constexpr int STAGES = 3;
    constexpr int ROWB   = 80;            // padded row stride (bytes) for 32 fp16
    constexpr int TILEB  = 128 * ROWB;    // 10240 B per operand tile
    constexpr int STAGEB = 3 * TILEB;     // 30720 B per stage (A, Bh, Bl)

    extern __shared__ char smem[];
    uint32_t sb = smem_u32(smem);
    int tid = threadIdx.x, lane = tid & 31, wid = tid >> 5;
    int bm = blockIdx.y * 128, bn = blockIdx.x * 128;
    int warp_m = wid >> 2, warp_n = wid & 3;

    const __half* srcs[3] = { A + (size_t)bm * K, Bh + (size_t)bn * K,
                              Bl + (size_t)bn * K };
    int nch = K >> 5;

    int g = lane >> 3;
    uint32_t rowsel = (uint32_t)(((g & 1) << 3) + (lane & 7));
    uint32_t colsel = (uint32_t)((g >> 1) * 16);

    float acc1[4][4][4], acc2[4][4][4];
    #pragma unroll
    for (int i = 0; i < 4; i++)
        #pragma unroll
        for (int j = 0; j < 4; j++)
            #pragma unroll
            for (int q = 0; q < 4; q++) { acc1[i][j][q] = 0.f; acc2[i][j][q] = 0.f; }

    auto issue = [&](int ch) {
        int k0 = ch << 5;
        uint32_t sbase = sb + (uint32_t)(ch % STAGES) * STAGEB;
        #pragma unroll
        for (int j = 0; j < 6; j++) {
            int c2 = j * 256 + tid;               // 0..1535
            int op = c2 >> 9, idx = c2 & 511, row = idx >> 2, ck = idx & 3;
            const __half* gp = srcs[op] + (size_t)row * K + k0 + ck * 8;
            uint32_t sa = sbase + (uint32_t)(op * TILEB + row * ROWB + ck * 16);
            CP_ASYNC16(sa, gp);
        }
    };

    #pragma unroll
    for (int s = 0; s < STAGES; s++) { issue(s); CP_COMMIT(); }

    for (int c = 0; c < nch; c++) {
        CP_WAIT(STAGES - 1);
        __syncthreads();
        uint32_t st = sb + (uint32_t)((c % STAGES) * STAGEB);

        #pragma unroll
        for (int kh2 = 0; kh2 < 2; kh2++) {
            uint32_t kb = (uint32_t)(kh2 * 32) + colsel;
            uint32_t af[4][4], bhf[2][4], blf[2][4];
            #pragma unroll
            for (int mi = 0; mi < 4; mi++) {
                uint32_t r = (uint32_t)(warp_m * 64 + mi * 16) + rowsel;
                ldsm4(af[mi], st + r * ROWB + kb);
            }
            #pragma unroll
            for (int ni = 0; ni < 2; ni++) {
                uint32_t r = (uint32_t)(warp_n * 32 + ni * 16) + rowsel;
                ldsm4(bhf[ni], st + TILEB + r * ROWB + kb);
                ldsm4(blf[ni], st + 2 * TILEB + r * ROWB + kb);
            }
            #pragma unroll
            for (int mi = 0; mi < 4; mi++)
                #pragma unroll
                for (int nj = 0; nj < 4; nj++)
                    mma_h(acc1[mi][nj], af[mi], bhf[nj >> 1][nj & 1], bhf[nj >> 1][(nj & 1) + 2]);
            #pragma unroll
            for (int mi = 0; mi < 4; mi++)
                #pragma unroll
                for (int nj = 0; nj < 4; nj++)
                    mma_h(acc2[mi][nj], af[mi], blf[nj >> 1][nj & 1], blf[nj >> 1][(nj & 1) + 2]);
        }
        __syncthreads();
        if (c + STAGES < nch) issue(c + STAGES);
        CP_COMMIT();
    }

    // ---- epilogue ----
    #pragma unroll
    for (int mi = 0; mi < 4; mi++) {
        int r0 = bm + warp_m * 64 + mi * 16 + (lane >> 2);
        #pragma unroll
        for (int nj = 0; nj < 4; nj++) {
            int cc = bn + warp_n * 32 + nj * 8 + (lane & 3) * 2;
            float b0 = bias[cc], b1 = bias[cc + 1];
            #pragma unroll
            for (int half = 0; half < 2; half++) {
                int r = r0 + half * 8;
                float v0 = acc1[mi][nj][half * 2 + 0]
                         + acc2[mi][nj][half * 2 + 0] * INV2048 + b0;
                float v1 = acc1[mi][nj][half * 2 + 1]
                         + acc2[mi][nj][half * 2 + 1] * INV2048 + b1;
                if (EPI == 2) {
                    size_t o = (size_t)r * N + cc;
                    v0 = 0.5f * v0 * (1.0f + erff(v0 * 0.70710678118654752f));
                    v1 = 0.5f * v1 * (1.0f + erff(v1 * 0.70710678118654752f));
                    *(uint32_t*)(Ch + o) = packh2(v0, v1);
                } else if (EPI == 3) {
                    size_t o = (size_t)r * N + cc;
                    v0 += res[o];
                    v1 += res[o + 1];
                    float2 f2; f2.x = v0; f2.y = v1;
                    *(float2*)(Cf + o) = f2;
                } else {  // EPI == 4: scatter qkv -> per-head bf16 hi/lo layout
                    int sel = cc >> 10, hh = (cc >> 6) & 15, d = cc & 63;
                    int bb = r >> 10, nn = r & 1023;
                    size_t o = ((size_t)((bb << 4) + hh) * SEQ + nn) * 64 + d;
                    __nv_bfloat16* dh = (sel == 0) ? Qh : (sel == 1) ? Kh : Vh;
                    __nv_bfloat16* dl = (sel == 0) ? Qlo : (sel == 1) ? Klo : Vlo;
                    __nv_bfloat16 h0 = __float2bfloat16(v0);
                    __nv_bfloat16 h1 = __float2bfloat16(v1);
                    *(uint32_t*)(dh + o) = packbf2(v0, v1);
                    *(uint32_t*)(dl + o) = packbf2(v0 - __bfloat162float(h0),
                                                   v1 - __bfloat162float(h1));
                }
            }
        }
    }
}

// ----------------------------------------------------------------------------
// Fused flash attention (bf16x3, unchanged core). Output: single fp16 [tok][DIM].
__global__ void __launch_bounds__(256, 1)
flash_kernel(const __nv_bfloat16* __restrict__ Qh, const __nv_bfloat16* __restrict__ Ql,
             const __nv_bfloat16* __restrict__ Kh, const __nv_bfloat16* __restrict__ Kl,
             const __nv_bfloat16* __restrict__ Vh, const __nv_bfloat16* __restrict__ Vl,
             __half* __restrict__ O) {
    constexpr int RSTR  = 144;
    constexpr int KVT   = 64 * RSTR;
    constexpr int STAGEB = 4 * KVT;
    constexpr int QB    = 128 * RSTR;

    extern __shared__ char smem[];
    uint32_t sb = smem_u32(smem);
    int tid = threadIdx.x, lane = tid & 31, wid = tid >> 5;
    int bh = blockIdx.y, i0 = blockIdx.x * 128;
    size_t seqb = (size_t)bh * SEQ * 64;

    {
        const __nv_bfloat16* qs[2] = { Qh + seqb + (size_t)i0 * 64,
                                       Ql + seqb + (size_t)i0 * 64 };
        #pragma unroll
        for (int j = 0; j < 8; j++) {
            int idx = j * 256 + tid;
            int op = idx >> 10, rem = idx & 1023, row = rem >> 3, ck = rem & 7;
            CP_ASYNC16(sb + (uint32_t)(op * QB + row * RSTR + ck * 16),
                       qs[op] + (size_t)row * 64 + ck * 8);
        }
        CP_COMMIT();
    }
    const __nv_bfloat16* kvs[4] = { Kh + seqb, Kl + seqb, Vh + seqb, Vl + seqb };
    auto issueKV = [&](int it) {
        int k0 = it * 64;
        uint32_t base = sb + 2 * QB + (uint32_t)(it & 1) * STAGEB;
        #pragma unroll
        for (int j = 0; j < 8; j++) {
            int idx = j * 256 + tid;
            int op = idx >> 9, rem = idx & 511, row = rem >> 3, ck = rem & 7;
            CP_ASYNC16(base + (uint32_t)(op * KVT + row * RSTR + ck * 16),
                       kvs[op] + (size_t)(k0 + row) * 64 + ck * 8);
        }
    };
    issueKV(0); CP_COMMIT();
    issueKV(1); CP_COMMIT();

    int g = lane >> 3;
    uint32_t lrow = (uint32_t)(((g & 1) << 3) + (lane & 7));
    uint32_t lcol = (uint32_t)((g >> 1) * 16);

    CP_WAIT(2);
    __syncthreads();
    uint32_t qfh[4][4], qfl[4][4];
    {
        int r0 = wid * 16;
        #pragma unroll
        for (int c = 0; c < 4; c++) {
            ldsm4(qfh[c], sb + (uint32_t)((r0 + lrow) * RSTR + c * 32) + lcol);
            ldsm4(qfl[c], sb + QB + (uint32_t)((r0 + lrow) * RSTR + c * 32) + lcol);
        }
    }

    float m0 = -1e30f, m1 = -1e30f, l0 = 0.f, l1 = 0.f;
    float o[8][4];
    #pragma unroll
    for (int nb = 0; nb < 8; nb++)
        #pragma unroll
        for (int q = 0; q < 4; q++) o[nb][q] = 0.f;

    for (int it = 0; it < 16; it++) {
        CP_WAIT(1);
        __syncthreads();
        uint32_t st = sb + 2 * QB + (uint32_t)(it & 1) * STAGEB;

        float s[8][4];
        #pragma unroll
        for (int nb = 0; nb < 8; nb++)
            #pragma unroll
            for (int q = 0; q < 4; q++) s[nb][q] = 0.f;

        #pragma unroll
        for (int c = 0; c < 4; c++) {
            uint32_t kfh[4][4], kfl[4][4];
            #pragma unroll
            for (int p = 0; p < 4; p++) {
                uint32_t a = st + (uint32_t)((p * 16 + lrow) * RSTR + c * 32) + lcol;
                ldsm4(kfh[p], a);
                ldsm4(kfl[p], a + KVT);
            }
            #pragma unroll
            for (int p = 0; p < 4; p++) {
                mma16816(s[2 * p],     qfh[c], kfh[p][0], kfh[p][2]);
                mma16816(s[2 * p + 1], qfh[c], kfh[p][1], kfh[p][3]);
                mma16816(s[2 * p],     qfh[c], kfl[p][0], kfl[p][2]);
                mma16816(s[2 * p + 1], qfh[c], kfl[p][1], kfl[p][3]);
                mma16816(s[2 * p],     qfl[c], kfh[p][0], kfh[p][2]);
                mma16816(s[2 * p + 1], qfl[c], kfh[p][1], kfh[p][3]);
            }
        }

        float rm0 = -1e30f, rm1 = -1e30f;
        #pragma unroll
        for (int nb = 0; nb < 8; nb++) {
            #pragma unroll
            for (int q = 0; q < 4; q++) s[nb][q] *= SCALE;
            rm0 = fmaxf(rm0, fmaxf(s[nb][0], s[nb][1]));
            rm1 = fmaxf(rm1, fmaxf(s[nb][2], s[nb][3]));
        }
        rm0 = fmaxf(rm0, __shfl_xor_sync(0xffffffffu, rm0, 1));
        rm0 = fmaxf(rm0, __shfl_xor_sync(0xffffffffu, rm0, 2));
        rm1 = fmaxf(rm1, __shfl_xor_sync(0xffffffffu, rm1, 1));
        rm1 = fmaxf(rm1, __shfl_xor_sync(0xffffffffu, rm1, 2));
        float nm0 = fmaxf(m0, rm0), nm1 = fmaxf(m1, rm1);
        float a0 = __expf(m0 - nm0), a1 = __expf(m1 - nm1);
        m0 = nm0; m1 = nm1;

        float sum0 = 0.f, sum1 = 0.f;
        uint32_t pfh[4][4], pfl[4][4];
        #pragma unroll
        for (int nb = 0; nb < 8; nb++) {
            float p00 = __expf(s[nb][0] - nm0);
            float p01 = __expf(s[nb][1] - nm0);
            float p10 = __expf(s[nb][2] - nm1);
            float p11 = __expf(s[nb][3] - nm1);
            sum0 += p00 + p01;
            sum1 += p10 + p11;
            float h00 = __bfloat162float(__float2bfloat16(p00));
            float h01 = __bfloat162float(__float2bfloat16(p01));
            float h10 = __bfloat162float(__float2bfloat16(p10));
            float h11 = __bfloat162float(__float2bfloat16(p11));
            int c = nb >> 1, off = (nb & 1) ? 2 : 0;
            pfh[c][off + 0] = packbf2(h00, h01);
            pfh[c][off + 1] = packbf2(h10, h11);
            pfl[c][off + 0] = packbf2(p00 - h00, p01 - h01);
            pfl[c][off + 1] = packbf2(p10 - h10, p11 - h11);
        }
        sum0 += __shfl_xor_sync(0xffffffffu, sum0, 1);
        sum0 += __shfl_xor_sync(0xffffffffu, sum0, 2);
        sum1 += __shfl_xor_sync(0xffffffffu, sum1, 1);
        sum1 += __shfl_xor_sync(0xffffffffu, sum1, 2);
        l0 = l0 * a0 + sum0;
        l1 = l1 * a1 + sum1;
        #pragma unroll
        for (int nb = 0; nb < 8; nb++) {
            o[nb][0] *= a0; o[nb][1] *= a0;
            o[nb][2] *= a1; o[nb][3] *= a1;
        }

        #pragma unroll
        for (int c = 0; c < 4; c++) {
            uint32_t vfh[4][4], vfl[4][4];
            #pragma unroll
            for (int dp = 0; dp < 4; dp++) {
                uint32_t a = st + 2 * KVT + (uint32_t)((c * 16 + lrow) * RSTR + dp * 32) + lcol;
                ldsm4t(vfh[dp], a);
                ldsm4t(vfl[dp], a + KVT);
            }
            #pragma unroll
            for (int dp = 0; dp < 4; dp++) {
                mma16816(o[2 * dp],     pfh[c], vfh[dp][0], vfh[dp][1]);
                mma16816(o[2 * dp + 1], pfh[c], vfh[dp][2], vfh[dp][3]);
                mma16816(o[2 * dp],     pfh[c], vfl[dp][0], vfl[dp][1]);
                mma16816(o[2 * dp + 1], pfh[c], vfl[dp][2], vfl[dp][3]);
                mma16816(o[2 * dp],     pfl[c], vfh[dp][0], vfh[dp][1]);
                mma16816(o[2 * dp + 1], pfl[c], vfh[dp][2], vfh[dp][3]);
            }
        }
        __syncthreads();
        if (it + 2 < 16) issueKV(it + 2);
        CP_COMMIT();
    }

    float inv0 = 1.0f / l0, inv1 = 1.0f / l1;
    int b = bh >> 4, h = bh & 15;
    int nrow = i0 + wid * 16 + (lane >> 2);
    size_t t0 = (size_t)b * SEQ + nrow;
    #pragma unroll
    for (int nb = 0; nb < 8; nb++) {
        int col = h * 64 + nb * 8 + (lane & 3) * 2;
        float v0 = o[nb][0] * inv0, v1 = o[nb][1] * inv0;
        float v2 = o[nb][2] * inv1, v3 = o[nb][3] * inv1;
        *(uint32_t*)(O + t0 * DIM + col) = packh2(v0, v1);
        *(uint32_t*)(O + (t0 + 8) * DIM + col) = packh2(v2, v3);
    }
}

// ----------------------------------------------------------------------------
extern "C" void kernel_launch(void* const* d_in, const int* in_sizes, int n_in,
                              void* d_out, int out_size) {
    const float* x_in   = (const float*)d_in[0];
    const float* ln1_w  = (const float*)d_in[1];
    const float* ln1_b  = (const float*)d_in[2];
    const float* qkv_w  = (const float*)d_in[3];
    const float* qkv_b  = (const float*)d_in[4];
    const float* proj_w = (const float*)d_in[5];
    const float* proj_b = (const float*)d_in[6];
    const float* ln2_w  = (const float*)d_in[7];
    const float* ln2_b  = (const float*)d_in[8];
    const float* mlp_w1 = (const float*)d_in[9];
    const float* mlp_b1 = (const float*)d_in[10];
    const float* mlp_w2 = (const float*)d_in[11];
    const float* mlp_b2 = (const float*)d_in[12];
    float* out = (float*)d_out;

    float *px;
    __half *py, *pa, *ph;
    __nv_bfloat16 *pqh, *pql, *pkh, *pkl, *pvh, *pvl;
    __half *wqh, *wql, *wph, *wpl, *w1h, *w1l, *w2h, *w2l;
    cudaGetSymbolAddress((void**)&px,   g_x);
    cudaGetSymbolAddress((void**)&py,   g_y);
    cudaGetSymbolAddress((void**)&pa,   g_a);
    cudaGetSymbolAddress((void**)&ph,   g_h);
    cudaGetSymbolAddress((void**)&pqh,  g_qh);
    cudaGetSymbolAddress((void**)&pql,  g_ql);
    cudaGetSymbolAddress((void**)&pkh,  g_kh);
    cudaGetSymbolAddress((void**)&pkl,  g_kl);
    cudaGetSymbolAddress((void**)&pvh,  g_vh);
    cudaGetSymbolAddress((void**)&pvl,  g_vl);
    cudaGetSymbolAddress((void**)&wqh,  g_wq_h);
    cudaGetSymbolAddress((void**)&wql,  g_wq_l);
    cudaGetSymbolAddress((void**)&wph,  g_wp_h);
    cudaGetSymbolAddress((void**)&wpl,  g_wp_l);
    cudaGetSymbolAddress((void**)&w1h,  g_w1_h);
    cudaGetSymbolAddress((void**)&w1l,  g_w1_l);
    cudaGetSymbolAddress((void**)&w2h,  g_w2_h);
    cudaGetSymbolAddress((void**)&w2l,  g_w2_l);

    const int SMEMSZ  = 3 * 3 * 128 * 80;                  // 92160 B (gemm)
    const int FSMEMSZ = 2 * 128 * 144 + 2 * 4 * 64 * 144;  // 110592 B (flash)
    cudaFuncSetAttribute(gemm_mma<2>, cudaFuncAttributeMaxDynamicSharedMemorySize, SMEMSZ);
    cudaFuncSetAttribute(gemm_mma<3>, cudaFuncAttributeMaxDynamicSharedMemorySize, SMEMSZ);
    cudaFuncSetAttribute(gemm_mma<4>, cudaFuncAttributeMaxDynamicSharedMemorySize, SMEMSZ);
    cudaFuncSetAttribute(flash_kernel, cudaFuncAttributeMaxDynamicSharedMemorySize, FSMEMSZ);

    // weight transpose + fp16 split
    dim3 blk(32, 8);
    wconvert<<<dim3(3 * DIM / 32, DIM / 32, DEPTH), blk>>>(qkv_w,  wqh, wql, DIM,  3 * DIM);
    wconvert<<<dim3(DIM / 32,     DIM / 32, DEPTH), blk>>>(proj_w, wph, wpl, DIM,  DIM);
    wconvert<<<dim3(MLPD / 32,    DIM / 32, DEPTH), blk>>>(mlp_w1, w1h, w1l, DIM,  MLPD);
    wconvert<<<dim3(DIM / 32,    MLPD / 32, DEPTH), blk>>>(mlp_w2, w2h, w2l, MLPD, DIM);

    const int nx = TOK * DIM;
    copy_kernel<<<(nx + 255) / 256, 256>>>(x_in, px, nx);

    for (int l = 0; l < DEPTH; l++) {
        size_t oq = (size_t)l * 3 * DIM * DIM;
        size_t op = (size_t)l * DIM * DIM;
        size_t o1 = (size_t)l * MLPD * DIM;
        size_t o2 = (size_t)l * DIM * MLPD;

        // ---- attention sublayer ----
        ln_half<<<TOK / 8, 256>>>(px, ln1_w + (size_t)l * DIM, ln1_b + (size_t)l * DIM, py);
        gemm_mma<4><<<dim3(3 * DIM / 128, TOK / 128), 256, SMEMSZ>>>(
            py, wqh + oq, wql + oq, qkv_b + (size_t)l * 3 * DIM, nullptr,
            nullptr, nullptr,
            pqh, pql, pkh, pkl, pvh, pvl, TOK, 3 * DIM, DIM);
        flash_kernel<<<dim3(8, BATCH * HEADS), 256, FSMEMSZ>>>(
            pqh, pql, pkh, pkl, pvh, pvl, pa);
        gemm_mma<3><<<dim3(DIM / 128, TOK / 128), 256, SMEMSZ>>>(
            pa, wph + op, wpl + op, proj_b + (size_t)l * DIM, px,
            px, nullptr,
            nullptr, nullptr, nullptr, nullptr, nullptr, nullptr, TOK, DIM, DIM);

        // ---- MLP sublayer ----
        ln_half<<<TOK / 8, 256>>>(px, ln2_w + (size_t)l * DIM, ln2_b + (size_t)l * DIM, py);
        gemm_mma<2><<<dim3(MLPD / 128, TOK / 128), 256, SMEMSZ>>>(
            py, w1h + o1, w1l + o1, mlp_b1 + (size_t)l * MLPD, nullptr,
            nullptr, ph,
            nullptr, nullptr, nullptr, nullptr, nullptr, nullptr, TOK, MLPD, DIM);
        gemm_mma<3><<<dim3(DIM / 128, TOK / 128), 256, SMEMSZ>>>(
            ph, w2h + o2, w2l + o2, mlp_b2 + (size_t)l * DIM, px,
            px, nullptr,
            nullptr, nullptr, nullptr, nullptr, nullptr, nullptr, TOK, DIM, MLPD);
    }

    copy_kernel<<<(nx + 255) / 256, 256>>>(px, out, nx);
}

// round 8
// speedup vs baseline: 5.0626x; 1.5008x over previous
#include <cuda_runtime.h>
#include <cuda_bf16.h>
#include <cuda_fp16.h>
#include <math.h>
#include <stdint.h>

// ----------------------------------------------------------------------------
// Transformer forward: 6 layers, B=4, N=1024, D=1024, H=16, hd=64, MLP=4096
// Round 8: dense GEMMs single-product fp16 (at legacy-HMMA issue ceiling,
// halve the MMA count); flash attention unchanged (bf16x3).
// ----------------------------------------------------------------------------

static constexpr int BATCH  = 4;
static constexpr int SEQ    = 1024;
static constexpr int DIM    = 1024;
static constexpr int HEADS  = 16;
static constexpr int HD     = 64;
static constexpr int MLPD   = 4096;
static constexpr int DEPTH  = 6;
static constexpr int TOK    = BATCH * SEQ;          // 4096
static constexpr float EPS  = 1e-5f;
static constexpr float SCALE = 0.03125f;            // DIM^-0.5

// ---------------- scratch (device globals; no allocation) -------------------
__device__ float         g_x   [(size_t)TOK * DIM];
__device__ __half        g_y   [(size_t)TOK * DIM];   // LN out, fp16
__device__ __nv_bfloat16 g_qh  [(size_t)TOK * DIM];   // [bh][n][64] layouts
__device__ __nv_bfloat16 g_ql  [(size_t)TOK * DIM];
__device__ __nv_bfloat16 g_kh  [(size_t)TOK * DIM];
__device__ __nv_bfloat16 g_kl  [(size_t)TOK * DIM];
__device__ __nv_bfloat16 g_vh  [(size_t)TOK * DIM];
__device__ __nv_bfloat16 g_vl  [(size_t)TOK * DIM];
__device__ __half        g_a   [(size_t)TOK * DIM];   // attn out, fp16
__device__ __half        g_h   [(size_t)TOK * MLPD];  // MLP hidden, fp16

// transposed fp16 weights
__device__ __half g_wq[(size_t)DEPTH * 3 * DIM * DIM];
__device__ __half g_wp[(size_t)DEPTH * DIM * DIM];
__device__ __half g_w1[(size_t)DEPTH * MLPD * DIM];
__device__ __half g_w2[(size_t)DEPTH * DIM * MLPD];

// ---------------------------- PTX helpers -----------------------------------
__device__ __forceinline__ uint32_t smem_u32(const void* p) {
    uint32_t a;
    asm("{ .reg .u64 t; cvta.to.shared.u64 t, %1; cvt.u32.u64 %0, t; }"
        : "=r"(a) : "l"(p));
    return a;
}

__device__ __forceinline__ void ldsm4(uint32_t* r, uint32_t a) {
    asm volatile("ldmatrix.sync.aligned.m8n8.x4.shared.b16 {%0,%1,%2,%3}, [%4];"
        : "=r"(r[0]), "=r"(r[1]), "=r"(r[2]), "=r"(r[3]) : "r"(a));
}
__device__ __forceinline__ void ldsm4t(uint32_t* r, uint32_t a) {
    asm volatile("ldmatrix.sync.aligned.m8n8.x4.trans.shared.b16 {%0,%1,%2,%3}, [%4];"
        : "=r"(r[0]), "=r"(r[1]), "=r"(r[2]), "=r"(r[3]) : "r"(a));
}

// bf16 MMA (flash)
__device__ __forceinline__ void mma16816(float* c, const uint32_t* a,
                                         uint32_t b0, uint32_t b1) {
    asm volatile("mma.sync.aligned.m16n8k16.row.col.f32.bf16.bf16.f32 "
        "{%0,%1,%2,%3}, {%4,%5,%6,%7}, {%8,%9}, {%0,%1,%2,%3};"
        : "+f"(c[0]), "+f"(c[1]), "+f"(c[2]), "+f"(c[3])
        : "r"(a[0]), "r"(a[1]), "r"(a[2]), "r"(a[3]), "r"(b0), "r"(b1));
}
// fp16 MMA (dense GEMMs)
__device__ __forceinline__ void mma_h(float* c, const uint32_t* a,
                                      uint32_t b0, uint32_t b1) {
    asm volatile("mma.sync.aligned.m16n8k16.row.col.f32.f16.f16.f32 "
        "{%0,%1,%2,%3}, {%4,%5,%6,%7}, {%8,%9}, {%0,%1,%2,%3};"
        : "+f"(c[0]), "+f"(c[1]), "+f"(c[2]), "+f"(c[3])
        : "r"(a[0]), "r"(a[1]), "r"(a[2]), "r"(a[3]), "r"(b0), "r"(b1));
}

#define CP_ASYNC16(saddr, gptr) \
    asm volatile("cp.async.cg.shared.global [%0], [%1], 16;" :: "r"(saddr), "l"(gptr))
#define CP_COMMIT() asm volatile("cp.async.commit_group;" ::: "memory")
#define CP_WAIT(n)  asm volatile("cp.async.wait_group %0;" :: "n"(n) : "memory")

__device__ __forceinline__ uint32_t packbf2(float x, float y) {
    __nv_bfloat162 p = __floats2bfloat162_rn(x, y);
    return *(uint32_t*)&p;
}
__device__ __forceinline__ uint32_t packh2(float x, float y) {
    __half2 p = __floats2half2_rn(x, y);
    return *(uint32_t*)&p;
}

// ----------------------------------------------------------------------------
__global__ void copy_kernel(const float* __restrict__ in, float* __restrict__ out, int n) {
    int i = blockIdx.x * blockDim.x + threadIdx.x;
    if (i < n) out[i] = in[i];
}

// ----------------------------------------------------------------------------
// Weight transpose to fp16: W [L,K,N] fp32 -> Wt [L,N,K] fp16
__global__ void wconvert(const float* __restrict__ W, __half* __restrict__ Th,
                         int K, int N) {
    __shared__ float t[32][33];
    size_t loff = (size_t)blockIdx.z * K * N;
    const float* Wl = W + loff;
    int n0 = blockIdx.x * 32, k0 = blockIdx.y * 32;
    #pragma unroll
    for (int i = 0; i < 4; i++) {
        int k = k0 + threadIdx.y + i * 8;
        t[threadIdx.y + i * 8][threadIdx.x] = Wl[(size_t)k * N + n0 + threadIdx.x];
    }
    __syncthreads();
    #pragma unroll
    for (int i = 0; i < 4; i++) {
        int n = n0 + threadIdx.y + i * 8;
        float v = t[threadIdx.x][threadIdx.y + i * 8];
        Th[loff + (size_t)n * K + k0 + threadIdx.x] = __float2half_rn(v);
    }
}

// ----------------------------------------------------------------------------
// LayerNorm: warp per row, one pass (sum + sumsq), fp16 output.
__global__ void ln_half(const float* __restrict__ x,
                        const float* __restrict__ w,
                        const float* __restrict__ b,
                        __half* __restrict__ y) {
    int row = blockIdx.x * 8 + (threadIdx.x >> 5);
    int lane = threadIdx.x & 31;
    const float4* xr = (const float4*)(x + (size_t)row * DIM);
    const float4* w4 = (const float4*)w;
    const float4* b4 = (const float4*)b;

    float4 v[8];
    float s = 0.f, s2 = 0.f;
    #pragma unroll
    for (int i = 0; i < 8; i++) {
        v[i] = xr[lane + i * 32];
        s  += v[i].x + v[i].y + v[i].z + v[i].w;
        s2 += v[i].x * v[i].x + v[i].y * v[i].y + v[i].z * v[i].z + v[i].w * v[i].w;
    }
    #pragma unroll
    for (int o = 16; o > 0; o >>= 1) {
        s  += __shfl_xor_sync(0xffffffffu, s,  o);
        s2 += __shfl_xor_sync(0xffffffffu, s2, o);
    }
    float mu = s * (1.0f / DIM);
    float var = s2 * (1.0f / DIM) - mu * mu;
    float rstd = rsqrtf(var + EPS);

    __half* yr = y + (size_t)row * DIM;
    #pragma unroll
    for (int i = 0; i < 8; i++) {
        int idx = (lane + i * 32);
        float4 wv = w4[idx], bv = b4[idx];
        float g0 = (v[i].x - mu) * rstd * wv.x + bv.x;
        float g1 = (v[i].y - mu) * rstd * wv.y + bv.y;
        float g2 = (v[i].z - mu) * rstd * wv.z + bv.z;
        float g3 = (v[i].w - mu) * rstd * wv.w + bv.w;
        uint2 pk;
        pk.x = packh2(g0, g1);
        pk.y = packh2(g2, g3);
        *(uint2*)(yr + idx * 4) = pk;
    }
}

// ----------------------------------------------------------------------------
// Dense GEMM, single-product fp16: C = A @ B (fp32 accum)
// A fp16 [M,K]; B fp16 [N,K] (K-major, pre-transposed).
// EPI: 2 = +bias,gelu -> fp16 Ch;  3 = +bias+res -> fp32 Cf;
//      4 = +bias -> scatter bf16 hi/lo QKV (per-head layout)
template<int EPI>
__global__ void __launch_bounds__(256, 1)
gemm_mma(const __half* __restrict__ A, const __half* __restrict__ B,
         const float* __restrict__ bias, const float* __restrict__ res,
         float* __restrict__ Cf, __half* __restrict__ Ch,
         __nv_bfloat16* __restrict__ Qh, __nv_bfloat16* __restrict__ Qlo,
         __nv_bfloat16* __restrict__ Kh, __nv_bfloat16* __restrict__ Klo,
         __nv_bfloat16* __restrict__ Vh, __nv_bfloat16* __restrict__ Vlo,
         int M, int N, int K) {
    constexpr int STAGES = 3;
    constexpr int ROWB   = 80;            // padded row stride (bytes) for 32 fp16
    constexpr int TILEB  = 128 * ROWB;    // 10240 B per operand tile
    constexpr int STAGEB = 2 * TILEB;     // 20480 B per stage (A, B)

    extern __shared__ char smem[];
    uint32_t sb = smem_u32(smem);
    int tid = threadIdx.x, lane = tid & 31, wid = tid >> 5;
    int bm = blockIdx.y * 128, bn = blockIdx.x * 128;
    int warp_m = wid >> 2, warp_n = wid & 3;

    const __half* srcs[2] = { A + (size_t)bm * K, B + (size_t)bn * K };
    int nch = K >> 5;

    int g = lane >> 3;
    uint32_t rowsel = (uint32_t)(((g & 1) << 3) + (lane & 7));
    uint32_t colsel = (uint32_t)((g >> 1) * 16);

    float acc[4][4][4];
    #pragma unroll
    for (int i = 0; i < 4; i++)
        #pragma unroll
        for (int j = 0; j < 4; j++)
            #pragma unroll
            for (int q = 0; q < 4; q++) acc[i][j][q] = 0.f;

    auto issue = [&](int ch) {
        int k0 = ch << 5;
        uint32_t sbase = sb + (uint32_t)(ch % STAGES) * STAGEB;
        #pragma unroll
        for (int j = 0; j < 4; j++) {
            int c2 = j * 256 + tid;               // 0..1023
            int op = c2 >> 9, idx = c2 & 511, row = idx >> 2, ck = idx & 3;
            const __half* gp = srcs[op] + (size_t)row * K + k0 + ck * 8;
            uint32_t sa = sbase + (uint32_t)(op * TILEB + row * ROWB + ck * 16);
            CP_ASYNC16(sa, gp);
        }
    };

    #pragma unroll
    for (int s = 0; s < STAGES; s++) { issue(s); CP_COMMIT(); }

    for (int c = 0; c < nch; c++) {
        CP_WAIT(STAGES - 1);
        __syncthreads();
        uint32_t st = sb + (uint32_t)((c % STAGES) * STAGEB);

        #pragma unroll
        for (int kh2 = 0; kh2 < 2; kh2++) {
            uint32_t kb = (uint32_t)(kh2 * 32) + colsel;
            uint32_t af[4][4], bf[2][4];
            #pragma unroll
            for (int mi = 0; mi < 4; mi++) {
                uint32_t r = (uint32_t)(warp_m * 64 + mi * 16) + rowsel;
                ldsm4(af[mi], st + r * ROWB + kb);
            }
            #pragma unroll
            for (int ni = 0; ni < 2; ni++) {
                uint32_t r = (uint32_t)(warp_n * 32 + ni * 16) + rowsel;
                ldsm4(bf[ni], st + TILEB + r * ROWB + kb);
            }
            #pragma unroll
            for (int mi = 0; mi < 4; mi++)
                #pragma unroll
                for (int nj = 0; nj < 4; nj++)
                    mma_h(acc[mi][nj], af[mi], bf[nj >> 1][nj & 1], bf[nj >> 1][(nj & 1) + 2]);
        }
        __syncthreads();
        if (c + STAGES < nch) issue(c + STAGES);
        CP_COMMIT();
    }

    // ---- epilogue ----
    #pragma unroll
    for (int mi = 0; mi < 4; mi++) {
        int r0 = bm + warp_m * 64 + mi * 16 + (lane >> 2);
        #pragma unroll
        for (int nj = 0; nj < 4; nj++) {
            int cc = bn + warp_n * 32 + nj * 8 + (lane & 3) * 2;
            float b0 = bias[cc], b1 = bias[cc + 1];
            #pragma unroll
            for (int half = 0; half < 2; half++) {
                int r = r0 + half * 8;
                float v0 = acc[mi][nj][half * 2 + 0] + b0;
                float v1 = acc[mi][nj][half * 2 + 1] + b1;
                if (EPI == 2) {
                    size_t o = (size_t)r * N + cc;
                    v0 = 0.5f * v0 * (1.0f + erff(v0 * 0.70710678118654752f));
                    v1 = 0.5f * v1 * (1.0f + erff(v1 * 0.70710678118654752f));
                    *(uint32_t*)(Ch + o) = packh2(v0, v1);
                } else if (EPI == 3) {
                    size_t o = (size_t)r * N + cc;
                    v0 += res[o];
                    v1 += res[o + 1];
                    float2 f2; f2.x = v0; f2.y = v1;
                    *(float2*)(Cf + o) = f2;
                } else {  // EPI == 4: scatter qkv -> per-head bf16 hi/lo layout
                    int sel = cc >> 10, hh = (cc >> 6) & 15, d = cc & 63;
                    int bb = r >> 10, nn = r & 1023;
                    size_t o = ((size_t)((bb << 4) + hh) * SEQ + nn) * 64 + d;
                    __nv_bfloat16* dh = (sel == 0) ? Qh : (sel == 1) ? Kh : Vh;
                    __nv_bfloat16* dl = (sel == 0) ? Qlo : (sel == 1) ? Klo : Vlo;
                    __nv_bfloat16 h0 = __float2bfloat16(v0);
                    __nv_bfloat16 h1 = __float2bfloat16(v1);
                    *(uint32_t*)(dh + o) = packbf2(v0, v1);
                    *(uint32_t*)(dl + o) = packbf2(v0 - __bfloat162float(h0),
                                                   v1 - __bfloat162float(h1));
                }
            }
        }
    }
}

// ----------------------------------------------------------------------------
// Fused flash attention (bf16x3, unchanged). Output: fp16 [tok][DIM].
__global__ void __launch_bounds__(256, 1)
flash_kernel(const __nv_bfloat16* __restrict__ Qh, const __nv_bfloat16* __restrict__ Ql,
             const __nv_bfloat16* __restrict__ Kh, const __nv_bfloat16* __restrict__ Kl,
             const __nv_bfloat16* __restrict__ Vh, const __nv_bfloat16* __restrict__ Vl,
             __half* __restrict__ O) {
    constexpr int RSTR  = 144;
    constexpr int KVT   = 64 * RSTR;
    constexpr int STAGEB = 4 * KVT;
    constexpr int QB    = 128 * RSTR;

    extern __shared__ char smem[];
    uint32_t sb = smem_u32(smem);
    int tid = threadIdx.x, lane = tid & 31, wid = tid >> 5;
    int bh = blockIdx.y, i0 = blockIdx.x * 128;
    size_t seqb = (size_t)bh * SEQ * 64;

    {
        const __nv_bfloat16* qs[2] = { Qh + seqb + (size_t)i0 * 64,
                                       Ql + seqb + (size_t)i0 * 64 };
        #pragma unroll
        for (int j = 0; j < 8; j++) {
            int idx = j * 256 + tid;
            int op = idx >> 10, rem = idx & 1023, row = rem >> 3, ck = rem & 7;
            CP_ASYNC16(sb + (uint32_t)(op * QB + row * RSTR + ck * 16),
                       qs[op] + (size_t)row * 64 + ck * 8);
        }
        CP_COMMIT();
    }
    const __nv_bfloat16* kvs[4] = { Kh + seqb, Kl + seqb, Vh + seqb, Vl + seqb };
    auto issueKV = [&](int it) {
        int k0 = it * 64;
        uint32_t base = sb + 2 * QB + (uint32_t)(it & 1) * STAGEB;
        #pragma unroll
        for (int j = 0; j < 8; j++) {
            int idx = j * 256 + tid;
            int op = idx >> 9, rem = idx & 511, row = rem >> 3, ck = rem & 7;
            CP_ASYNC16(base + (uint32_t)(op * KVT + row * RSTR + ck * 16),
                       kvs[op] + (size_t)(k0 + row) * 64 + ck * 8);
        }
    };
    issueKV(0); CP_COMMIT();
    issueKV(1); CP_COMMIT();

    int g = lane >> 3;
    uint32_t lrow = (uint32_t)(((g & 1) << 3) + (lane & 7));
    uint32_t lcol = (uint32_t)((g >> 1) * 16);

    CP_WAIT(2);
    __syncthreads();
    uint32_t qfh[4][4], qfl[4][4];
    {
        int r0 = wid * 16;
        #pragma unroll
        for (int c = 0; c < 4; c++) {
            ldsm4(qfh[c], sb + (uint32_t)((r0 + lrow) * RSTR + c * 32) + lcol);
            ldsm4(qfl[c], sb + QB + (uint32_t)((r0 + lrow) * RSTR + c * 32) + lcol);
        }
    }

    float m0 = -1e30f, m1 = -1e30f, l0 = 0.f, l1 = 0.f;
    float o[8][4];
    #pragma unroll
    for (int nb = 0; nb < 8; nb++)
        #pragma unroll
        for (int q = 0; q < 4; q++) o[nb][q] = 0.f;

    for (int it = 0; it < 16; it++) {
        CP_WAIT(1);
        __syncthreads();
        uint32_t st = sb + 2 * QB + (uint32_t)(it & 1) * STAGEB;

        float s[8][4];
        #pragma unroll
        for (int nb = 0; nb < 8; nb++)
            #pragma unroll
            for (int q = 0; q < 4; q++) s[nb][q] = 0.f;

        #pragma unroll
        for (int c = 0; c < 4; c++) {
            uint32_t kfh[4][4], kfl[4][4];
            #pragma unroll
            for (int p = 0; p < 4; p++) {
                uint32_t a = st + (uint32_t)((p * 16 + lrow) * RSTR + c * 32) + lcol;
                ldsm4(kfh[p], a);
                ldsm4(kfl[p], a + KVT);
            }
            #pragma unroll
            for (int p = 0; p < 4; p++) {
                mma16816(s[2 * p],     qfh[c], kfh[p][0], kfh[p][2]);
                mma16816(s[2 * p + 1], qfh[c], kfh[p][1], kfh[p][3]);
                mma16816(s[2 * p],     qfh[c], kfl[p][0], kfl[p][2]);
                mma16816(s[2 * p + 1], qfh[c], kfl[p][1], kfl[p][3]);
                mma16816(s[2 * p],     qfl[c], kfh[p][0], kfh[p][2]);
                mma16816(s[2 * p + 1], qfl[c], kfh[p][1], kfh[p][3]);
            }
        }

        float rm0 = -1e30f, rm1 = -1e30f;
        #pragma unroll
        for (int nb = 0; nb < 8; nb++) {
            #pragma unroll
            for (int q = 0; q < 4; q++) s[nb][q] *= SCALE;
            rm0 = fmaxf(rm0, fmaxf(s[nb][0], s[nb][1]));
            rm1 = fmaxf(rm1, fmaxf(s[nb][2], s[nb][3]));
        }
        rm0 = fmaxf(rm0, __shfl_xor_sync(0xffffffffu, rm0, 1));
        rm0 = fmaxf(rm0, __shfl_xor_sync(0xffffffffu, rm0, 2));
        rm1 = fmaxf(rm1, __shfl_xor_sync(0xffffffffu, rm1, 1));
        rm1 = fmaxf(rm1, __shfl_xor_sync(0xffffffffu, rm1, 2));
        float nm0 = fmaxf(m0, rm0), nm1 = fmaxf(m1, rm1);
        float a0 = __expf(m0 - nm0), a1 = __expf(m1 - nm1);
        m0 = nm0; m1 = nm1;

        float sum0 = 0.f, sum1 = 0.f;
        uint32_t pfh[4][4], pfl[4][4];
        #pragma unroll
        for (int nb = 0; nb < 8; nb++) {
            float p00 = __expf(s[nb][0] - nm0);
            float p01 = __expf(s[nb][1] - nm0);
            float p10 = __expf(s[nb][2] - nm1);
            float p11 = __expf(s[nb][3] - nm1);
            sum0 += p00 + p01;
            sum1 += p10 + p11;
            float h00 = __bfloat162float(__float2bfloat16(p00));
            float h01 = __bfloat162float(__float2bfloat16(p01));
            float h10 = __bfloat162float(__float2bfloat16(p10));
            float h11 = __bfloat162float(__float2bfloat16(p11));
            int c = nb >> 1, off = (nb & 1) ? 2 : 0;
            pfh[c][off + 0] = packbf2(h00, h01);
            pfh[c][off + 1] = packbf2(h10, h11);
            pfl[c][off + 0] = packbf2(p00 - h00, p01 - h01);
            pfl[c][off + 1] = packbf2(p10 - h10, p11 - h11);
        }
        sum0 += __shfl_xor_sync(0xffffffffu, sum0, 1);
        sum0 += __shfl_xor_sync(0xffffffffu, sum0, 2);
        sum1 += __shfl_xor_sync(0xffffffffu, sum1, 1);
        sum1 += __shfl_xor_sync(0xffffffffu, sum1, 2);
        l0 = l0 * a0 + sum0;
        l1 = l1 * a1 + sum1;
        #pragma unroll
        for (int nb = 0; nb < 8; nb++) {
            o[nb][0] *= a0; o[nb][1] *= a0;
            o[nb][2] *= a1; o[nb][3] *= a1;
        }

        #pragma unroll
        for (int c = 0; c < 4; c++) {
            uint32_t vfh[4][4], vfl[4][4];
            #pragma unroll
            for (int dp = 0; dp < 4; dp++) {
                uint32_t a = st + 2 * KVT + (uint32_t)((c * 16 + lrow) * RSTR + dp * 32) + lcol;
                ldsm4t(vfh[dp], a);
                ldsm4t(vfl[dp], a + KVT);
            }
            #pragma unroll
            for (int dp = 0; dp < 4; dp++) {
                mma16816(o[2 * dp],     pfh[c], vfh[dp][0], vfh[dp][1]);
                mma16816(o[2 * dp + 1], pfh[c], vfh[dp][2], vfh[dp][3]);
                mma16816(o[2 * dp],     pfh[c], vfl[dp][0], vfl[dp][1]);
                mma16816(o[2 * dp + 1], pfh[c], vfl[dp][2], vfl[dp][3]);
                mma16816(o[2 * dp],     pfl[c], vfh[dp][0], vfh[dp][1]);
                mma16816(o[2 * dp + 1], pfl[c], vfh[dp][2], vfh[dp][3]);
            }
        }
        __syncthreads();
        if (it + 2 < 16) issueKV(it + 2);
        CP_COMMIT();
    }

    float inv0 = 1.0f / l0, inv1 = 1.0f / l1;
    int b = bh >> 4, h = bh & 15;
    int nrow = i0 + wid * 16 + (lane >> 2);
    size_t t0 = (size_t)b * SEQ + nrow;
    #pragma unroll
    for (int nb = 0; nb < 8; nb++) {
        int col = h * 64 + nb * 8 + (lane & 3) * 2;
        float v0 = o[nb][0] * inv0, v1 = o[nb][1] * inv0;
        float v2 = o[nb][2] * inv1, v3 = o[nb][3] * inv1;
        *(uint32_t*)(O + t0 * DIM + col) = packh2(v0, v1);
        *(uint32_t*)(O + (t0 + 8) * DIM + col) = packh2(v2, v3);
    }
}

// ----------------------------------------------------------------------------
extern "C" void kernel_launch(void* const* d_in, const int* in_sizes, int n_in,
                              void* d_out, int out_size) {
    const float* x_in   = (const float*)d_in[0];
    const float* ln1_w  = (const float*)d_in[1];
    const float* ln1_b  = (const float*)d_in[2];
    const float* qkv_w  = (const float*)d_in[3];
    const float* qkv_b  = (const float*)d_in[4];
    const float* proj_w = (const float*)d_in[5];
    const float* proj_b = (const float*)d_in[6];
    const float* ln2_w  = (const float*)d_in[7];
    const float* ln2_b  = (const float*)d_in[8];
    const float* mlp_w1 = (const float*)d_in[9];
    const float* mlp_b1 = (const float*)d_in[10];
    const float* mlp_w2 = (const float*)d_in[11];
    const float* mlp_b2 = (const float*)d_in[12];
    float* out = (float*)d_out;

    float *px;
    __half *py, *pa, *ph;
    __nv_bfloat16 *pqh, *pql, *pkh, *pkl, *pvh, *pvl;
    __half *wq, *wp, *w1, *w2;
    cudaGetSymbolAddress((void**)&px,   g_x);
    cudaGetSymbolAddress((void**)&py,   g_y);
    cudaGetSymbolAddress((void**)&pa,   g_a);
    cudaGetSymbolAddress((void**)&ph,   g_h);
    cudaGetSymbolAddress((void**)&pqh,  g_qh);
    cudaGetSymbolAddress((void**)&pql,  g_ql);
    cudaGetSymbolAddress((void**)&pkh,  g_kh);
    cudaGetSymbolAddress((void**)&pkl,  g_kl);
    cudaGetSymbolAddress((void**)&pvh,  g_vh);
    cudaGetSymbolAddress((void**)&pvl,  g_vl);
    cudaGetSymbolAddress((void**)&wq,   g_wq);
    cudaGetSymbolAddress((void**)&wp,   g_wp);
    cudaGetSymbolAddress((void**)&w1,   g_w1);
    cudaGetSymbolAddress((void**)&w2,   g_w2);

    const int SMEMSZ  = 3 * 2 * 128 * 80;                  // 61440 B (gemm)
    const int FSMEMSZ = 2 * 128 * 144 + 2 * 4 * 64 * 144;  // 110592 B (flash)
    cudaFuncSetAttribute(gemm_mma<2>, cudaFuncAttributeMaxDynamicSharedMemorySize, SMEMSZ);
    cudaFuncSetAttribute(gemm_mma<3>, cudaFuncAttributeMaxDynamicSharedMemorySize, SMEMSZ);
    cudaFuncSetAttribute(gemm_mma<4>, cudaFuncAttributeMaxDynamicSharedMemorySize, SMEMSZ);
    cudaFuncSetAttribute(flash_kernel, cudaFuncAttributeMaxDynamicSharedMemorySize, FSMEMSZ);

    // weight transpose to fp16
    dim3 blk(32, 8);
    wconvert<<<dim3(3 * DIM / 32, DIM / 32, DEPTH), blk>>>(qkv_w,  wq, DIM,  3 * DIM);
    wconvert<<<dim3(DIM / 32,     DIM / 32, DEPTH), blk>>>(proj_w, wp, DIM,  DIM);
    wconvert<<<dim3(MLPD / 32,    DIM / 32, DEPTH), blk>>>(mlp_w1, w1, DIM,  MLPD);
    wconvert<<<dim3(DIM / 32,    MLPD / 32, DEPTH), blk>>>(mlp_w2, w2, MLPD, DIM);

    const int nx = TOK * DIM;
    copy_kernel<<<(nx + 255) / 256, 256>>>(x_in, px, nx);

    for (int l = 0; l < DEPTH; l++) {
        size_t oq = (size_t)l * 3 * DIM * DIM;
        size_t op = (size_t)l * DIM * DIM;
        size_t o1 = (size_t)l * MLPD * DIM;
        size_t o2 = (size_t)l * DIM * MLPD;

        // ---- attention sublayer ----
        ln_half<<<TOK / 8, 256>>>(px, ln1_w + (size_t)l * DIM, ln1_b + (size_t)l * DIM, py);
        gemm_mma<4><<<dim3(3 * DIM / 128, TOK / 128), 256, SMEMSZ>>>(
            py, wq + oq, qkv_b + (size_t)l * 3 * DIM, nullptr,
            nullptr, nullptr,
            pqh, pql, pkh, pkl, pvh, pvl, TOK, 3 * DIM, DIM);
        flash_kernel<<<dim3(8, BATCH * HEADS), 256, FSMEMSZ>>>(
            pqh, pql, pkh, pkl, pvh, pvl, pa);
        gemm_mma<3><<<dim3(DIM / 128, TOK / 128), 256, SMEMSZ>>>(
            pa, wp + op, proj_b + (size_t)l * DIM, px,
            px, nullptr,
            nullptr, nullptr, nullptr, nullptr, nullptr, nullptr, TOK, DIM, DIM);

        // ---- MLP sublayer ----
        ln_half<<<TOK / 8, 256>>>(px, ln2_w + (size_t)l * DIM, ln2_b + (size_t)l * DIM, py);
        gemm_mma<2><<<dim3(MLPD / 128, TOK / 128), 256, SMEMSZ>>>(
            py, w1 + o1, mlp_b1 + (size_t)l * MLPD, nullptr,
            nullptr, ph,
            nullptr, nullptr, nullptr, nullptr, nullptr, nullptr, TOK, MLPD, DIM);
        gemm_mma<3><<<dim3(DIM / 128, TOK / 128), 256, SMEMSZ>>>(
            ph, w2 + o2, mlp_b2 + (size_t)l * DIM, px,
            px, nullptr,
            nullptr, nullptr, nullptr, nullptr, nullptr, nullptr, TOK, DIM, MLPD);
    }

    copy_kernel<<<(nx + 255) / 256, 256>>>(px, out, nx);
}

// round 9
// speedup vs baseline: 6.0239x; 1.1899x over previous
#include <cuda_runtime.h>
#include <cuda_bf16.h>
#include <cuda_fp16.h>
#include <math.h>
#include <stdint.h>

// ----------------------------------------------------------------------------
// Transformer forward: 6 layers, B=4, N=1024, D=1024, H=16, hd=64, MLP=4096
// Round 9: everything single-product fp16 on HMMA (dense GEMMs + flash attn);
// residual-stream copies eliminated (layer-0 reads input, final writes d_out).
// ----------------------------------------------------------------------------

static constexpr int BATCH  = 4;
static constexpr int SEQ    = 1024;
static constexpr int DIM    = 1024;
static constexpr int HEADS  = 16;
static constexpr int HD     = 64;
static constexpr int MLPD   = 4096;
static constexpr int DEPTH  = 6;
static constexpr int TOK    = BATCH * SEQ;          // 4096
static constexpr float EPS  = 1e-5f;
static constexpr float SCALE = 0.03125f;            // DIM^-0.5

// ---------------- scratch (device globals; no allocation) -------------------
__device__ float  g_x [(size_t)TOK * DIM];
__device__ __half g_y [(size_t)TOK * DIM];   // LN out
__device__ __half g_q [(size_t)TOK * DIM];   // [bh][n][64]
__device__ __half g_k [(size_t)TOK * DIM];
__device__ __half g_v [(size_t)TOK * DIM];
__device__ __half g_a [(size_t)TOK * DIM];   // attn out [tok][DIM]
__device__ __half g_h [(size_t)TOK * MLPD];  // MLP hidden

// transposed fp16 weights
__device__ __half g_wq[(size_t)DEPTH * 3 * DIM * DIM];
__device__ __half g_wp[(size_t)DEPTH * DIM * DIM];
__device__ __half g_w1[(size_t)DEPTH * MLPD * DIM];
__device__ __half g_w2[(size_t)DEPTH * DIM * MLPD];

// ---------------------------- PTX helpers -----------------------------------
__device__ __forceinline__ uint32_t smem_u32(const void* p) {
    uint32_t a;
    asm("{ .reg .u64 t; cvta.to.shared.u64 t, %1; cvt.u32.u64 %0, t; }"
        : "=r"(a) : "l"(p));
    return a;
}

__device__ __forceinline__ void ldsm4(uint32_t* r, uint32_t a) {
    asm volatile("ldmatrix.sync.aligned.m8n8.x4.shared.b16 {%0,%1,%2,%3}, [%4];"
        : "=r"(r[0]), "=r"(r[1]), "=r"(r[2]), "=r"(r[3]) : "r"(a));
}
__device__ __forceinline__ void ldsm4t(uint32_t* r, uint32_t a) {
    asm volatile("ldmatrix.sync.aligned.m8n8.x4.trans.shared.b16 {%0,%1,%2,%3}, [%4];"
        : "=r"(r[0]), "=r"(r[1]), "=r"(r[2]), "=r"(r[3]) : "r"(a));
}

__device__ __forceinline__ void mma_h(float* c, const uint32_t* a,
                                      uint32_t b0, uint32_t b1) {
    asm volatile("mma.sync.aligned.m16n8k16.row.col.f32.f16.f16.f32 "
        "{%0,%1,%2,%3}, {%4,%5,%6,%7}, {%8,%9}, {%0,%1,%2,%3};"
        : "+f"(c[0]), "+f"(c[1]), "+f"(c[2]), "+f"(c[3])
        : "r"(a[0]), "r"(a[1]), "r"(a[2]), "r"(a[3]), "r"(b0), "r"(b1));
}

#define CP_ASYNC16(saddr, gptr) \
    asm volatile("cp.async.cg.shared.global [%0], [%1], 16;" :: "r"(saddr), "l"(gptr))
#define CP_COMMIT() asm volatile("cp.async.commit_group;" ::: "memory")
#define CP_WAIT(n)  asm volatile("cp.async.wait_group %0;" :: "n"(n) : "memory")

__device__ __forceinline__ uint32_t packh2(float x, float y) {
    __half2 p = __floats2half2_rn(x, y);
    return *(uint32_t*)&p;
}

// ----------------------------------------------------------------------------
// Weight transpose to fp16: W [L,K,N] fp32 -> Wt [L,N,K] fp16
__global__ void wconvert(const float* __restrict__ W, __half* __restrict__ Th,
                         int K, int N) {
    __shared__ float t[32][33];
    size_t loff = (size_t)blockIdx.z * K * N;
    const float* Wl = W + loff;
    int n0 = blockIdx.x * 32, k0 = blockIdx.y * 32;
    #pragma unroll
    for (int i = 0; i < 4; i++) {
        int k = k0 + threadIdx.y + i * 8;
        t[threadIdx.y + i * 8][threadIdx.x] = Wl[(size_t)k * N + n0 + threadIdx.x];
    }
    __syncthreads();
    #pragma unroll
    for (int i = 0; i < 4; i++) {
        int n = n0 + threadIdx.y + i * 8;
        float v = t[threadIdx.x][threadIdx.y + i * 8];
        Th[loff + (size_t)n * K + k0 + threadIdx.x] = __float2half_rn(v);
    }
}

// ----------------------------------------------------------------------------
// LayerNorm: warp per row, one pass (sum + sumsq), fp16 output.
__global__ void ln_half(const float* __restrict__ x,
                        const float* __restrict__ w,
                        const float* __restrict__ b,
                        __half* __restrict__ y) {
    int row = blockIdx.x * 8 + (threadIdx.x >> 5);
    int lane = threadIdx.x & 31;
    const float4* xr = (const float4*)(x + (size_t)row * DIM);
    const float4* w4 = (const float4*)w;
    const float4* b4 = (const float4*)b;

    float4 v[8];
    float s = 0.f, s2 = 0.f;
    #pragma unroll
    for (int i = 0; i < 8; i++) {
        v[i] = xr[lane + i * 32];
        s  += v[i].x + v[i].y + v[i].z + v[i].w;
        s2 += v[i].x * v[i].x + v[i].y * v[i].y + v[i].z * v[i].z + v[i].w * v[i].w;
    }
    #pragma unroll
    for (int o = 16; o > 0; o >>= 1) {
        s  += __shfl_xor_sync(0xffffffffu, s,  o);
        s2 += __shfl_xor_sync(0xffffffffu, s2, o);
    }
    float mu = s * (1.0f / DIM);
    float var = s2 * (1.0f / DIM) - mu * mu;
    float rstd = rsqrtf(var + EPS);

    __half* yr = y + (size_t)row * DIM;
    #pragma unroll
    for (int i = 0; i < 8; i++) {
        int idx = (lane + i * 32);
        float4 wv = w4[idx], bv = b4[idx];
        float g0 = (v[i].x - mu) * rstd * wv.x + bv.x;
        float g1 = (v[i].y - mu) * rstd * wv.y + bv.y;
        float g2 = (v[i].z - mu) * rstd * wv.z + bv.z;
        float g3 = (v[i].w - mu) * rstd * wv.w + bv.w;
        uint2 pk;
        pk.x = packh2(g0, g1);
        pk.y = packh2(g2, g3);
        *(uint2*)(yr + idx * 4) = pk;
    }
}

// ----------------------------------------------------------------------------
// Dense GEMM, single-product fp16: C = A @ B (fp32 accum)
// EPI: 2 = +bias,gelu -> fp16 Ch;  3 = +bias+res -> fp32 Cf;
//      4 = +bias -> scatter fp16 QKV (per-head layout)
template<int EPI>
__global__ void __launch_bounds__(256, 1)
gemm_mma(const __half* __restrict__ A, const __half* __restrict__ B,
         const float* __restrict__ bias, const float* __restrict__ res,
         float* __restrict__ Cf, __half* __restrict__ Ch,
         __half* __restrict__ Qp, __half* __restrict__ Kp, __half* __restrict__ Vp,
         int M, int N, int K) {
    constexpr int STAGES = 3;
    constexpr int ROWB   = 80;
    constexpr int TILEB  = 128 * ROWB;    // 10240 B per operand tile
    constexpr int STAGEB = 2 * TILEB;     // 20480 B per stage

    extern __shared__ char smem[];
    uint32_t sb = smem_u32(smem);
    int tid = threadIdx.x, lane = tid & 31, wid = tid >> 5;
    int bm = blockIdx.y * 128, bn = blockIdx.x * 128;
    int warp_m = wid >> 2, warp_n = wid & 3;

    const __half* srcs[2] = { A + (size_t)bm * K, B + (size_t)bn * K };
    int nch = K >> 5;

    int g = lane >> 3;
    uint32_t rowsel = (uint32_t)(((g & 1) << 3) + (lane & 7));
    uint32_t colsel = (uint32_t)((g >> 1) * 16);

    float acc[4][4][4];
    #pragma unroll
    for (int i = 0; i < 4; i++)
        #pragma unroll
        for (int j = 0; j < 4; j++)
            #pragma unroll
            for (int q = 0; q < 4; q++) acc[i][j][q] = 0.f;

    auto issue = [&](int ch) {
        int k0 = ch << 5;
        uint32_t sbase = sb + (uint32_t)(ch % STAGES) * STAGEB;
        #pragma unroll
        for (int j = 0; j < 4; j++) {
            int c2 = j * 256 + tid;
            int op = c2 >> 9, idx = c2 & 511, row = idx >> 2, ck = idx & 3;
            const __half* gp = srcs[op] + (size_t)row * K + k0 + ck * 8;
            uint32_t sa = sbase + (uint32_t)(op * TILEB + row * ROWB + ck * 16);
            CP_ASYNC16(sa, gp);
        }
    };

    #pragma unroll
    for (int s = 0; s < STAGES; s++) { issue(s); CP_COMMIT(); }

    for (int c = 0; c < nch; c++) {
        CP_WAIT(STAGES - 1);
        __syncthreads();
        uint32_t st = sb + (uint32_t)((c % STAGES) * STAGEB);

        #pragma unroll
        for (int kh2 = 0; kh2 < 2; kh2++) {
            uint32_t kb = (uint32_t)(kh2 * 32) + colsel;
            uint32_t af[4][4], bf[2][4];
            #pragma unroll
            for (int mi = 0; mi < 4; mi++) {
                uint32_t r = (uint32_t)(warp_m * 64 + mi * 16) + rowsel;
                ldsm4(af[mi], st + r * ROWB + kb);
            }
            #pragma unroll
            for (int ni = 0; ni < 2; ni++) {
                uint32_t r = (uint32_t)(warp_n * 32 + ni * 16) + rowsel;
                ldsm4(bf[ni], st + TILEB + r * ROWB + kb);
            }
            #pragma unroll
            for (int mi = 0; mi < 4; mi++)
                #pragma unroll
                for (int nj = 0; nj < 4; nj++)
                    mma_h(acc[mi][nj], af[mi], bf[nj >> 1][nj & 1], bf[nj >> 1][(nj & 1) + 2]);
        }
        __syncthreads();
        if (c + STAGES < nch) issue(c + STAGES);
        CP_COMMIT();
    }

    // ---- epilogue ----
    #pragma unroll
    for (int mi = 0; mi < 4; mi++) {
        int r0 = bm + warp_m * 64 + mi * 16 + (lane >> 2);
        #pragma unroll
        for (int nj = 0; nj < 4; nj++) {
            int cc = bn + warp_n * 32 + nj * 8 + (lane & 3) * 2;
            float b0 = bias[cc], b1 = bias[cc + 1];
            #pragma unroll
            for (int half = 0; half < 2; half++) {
                int r = r0 + half * 8;
                float v0 = acc[mi][nj][half * 2 + 0] + b0;
                float v1 = acc[mi][nj][half * 2 + 1] + b1;
                if (EPI == 2) {
                    size_t o = (size_t)r * N + cc;
                    v0 = 0.5f * v0 * (1.0f + erff(v0 * 0.70710678118654752f));
                    v1 = 0.5f * v1 * (1.0f + erff(v1 * 0.70710678118654752f));
                    *(uint32_t*)(Ch + o) = packh2(v0, v1);
                } else if (EPI == 3) {
                    size_t o = (size_t)r * N + cc;
                    v0 += res[o];
                    v1 += res[o + 1];
                    float2 f2; f2.x = v0; f2.y = v1;
                    *(float2*)(Cf + o) = f2;
                } else {  // EPI == 4: scatter qkv -> per-head fp16 layout
                    int sel = cc >> 10, hh = (cc >> 6) & 15, d = cc & 63;
                    int bb = r >> 10, nn = r & 1023;
                    size_t o = ((size_t)((bb << 4) + hh) * SEQ + nn) * 64 + d;
                    __half* dh = (sel == 0) ? Qp : (sel == 1) ? Kp : Vp;
                    *(uint32_t*)(dh + o) = packh2(v0, v1);
                }
            }
        }
    }
}

// ----------------------------------------------------------------------------
// Fused flash attention, single-product fp16.
// Per CTA: one (b,h), 128 Q rows; 16 KV tiles of 64 keys, double-buffered.
__global__ void __launch_bounds__(256, 1)
flash_kernel(const __half* __restrict__ Q, const __half* __restrict__ K,
             const __half* __restrict__ V, __half* __restrict__ O) {
    constexpr int RSTR   = 144;           // padded row stride (64 fp16 + 16B)
    constexpr int KVT    = 64 * RSTR;     // 9216 B per operand tile
    constexpr int STAGEB = 2 * KVT;       // 18432 B per stage (K, V)
    constexpr int QB     = 128 * RSTR;    // 18432 B

    extern __shared__ char smem[];
    uint32_t sb = smem_u32(smem);
    int tid = threadIdx.x, lane = tid & 31, wid = tid >> 5;
    int bh = blockIdx.y, i0 = blockIdx.x * 128;
    size_t seqb = (size_t)bh * SEQ * 64;

    // --- Q load ---
    {
        const __half* qsrc = Q + seqb + (size_t)i0 * 64;
        #pragma unroll
        for (int j = 0; j < 4; j++) {
            int idx = j * 256 + tid;           // 0..1023
            int row = idx >> 3, ck = idx & 7;
            CP_ASYNC16(sb + (uint32_t)(row * RSTR + ck * 16),
                       qsrc + (size_t)row * 64 + ck * 8);
        }
        CP_COMMIT();
    }
    const __half* kvs[2] = { K + seqb, V + seqb };
    auto issueKV = [&](int it) {
        int k0 = it * 64;
        uint32_t base = sb + QB + (uint32_t)(it & 1) * STAGEB;
        #pragma unroll
        for (int j = 0; j < 4; j++) {
            int idx = j * 256 + tid;           // 0..1023
            int op = idx >> 9, rem = idx & 511, row = rem >> 3, ck = rem & 7;
            CP_ASYNC16(base + (uint32_t)(op * KVT + row * RSTR + ck * 16),
                       kvs[op] + (size_t)(k0 + row) * 64 + ck * 8);
        }
    };
    issueKV(0); CP_COMMIT();
    issueKV(1); CP_COMMIT();

    int g = lane >> 3;
    uint32_t lrow = (uint32_t)(((g & 1) << 3) + (lane & 7));
    uint32_t lcol = (uint32_t)((g >> 1) * 16);

    // --- Q fragments in registers ---
    CP_WAIT(2);
    __syncthreads();
    uint32_t qf[4][4];
    {
        int r0 = wid * 16;
        #pragma unroll
        for (int c = 0; c < 4; c++)
            ldsm4(qf[c], sb + (uint32_t)((r0 + lrow) * RSTR + c * 32) + lcol);
    }

    float m0 = -1e30f, m1 = -1e30f, l0 = 0.f, l1 = 0.f;
    float o[8][4];
    #pragma unroll
    for (int nb = 0; nb < 8; nb++)
        #pragma unroll
        for (int q = 0; q < 4; q++) o[nb][q] = 0.f;

    for (int it = 0; it < 16; it++) {
        CP_WAIT(1);
        __syncthreads();
        uint32_t st = sb + QB + (uint32_t)(it & 1) * STAGEB;

        // ---- S = Q K^T ----
        float s[8][4];
        #pragma unroll
        for (int nb = 0; nb < 8; nb++)
            #pragma unroll
            for (int q = 0; q < 4; q++) s[nb][q] = 0.f;

        #pragma unroll
        for (int c = 0; c < 4; c++) {
            uint32_t kf[4][4];
            #pragma unroll
            for (int p = 0; p < 4; p++)
                ldsm4(kf[p], st + (uint32_t)((p * 16 + lrow) * RSTR + c * 32) + lcol);
            #pragma unroll
            for (int p = 0; p < 4; p++) {
                mma_h(s[2 * p],     qf[c], kf[p][0], kf[p][2]);
                mma_h(s[2 * p + 1], qf[c], kf[p][1], kf[p][3]);
            }
        }

        // ---- online softmax ----
        float rm0 = -1e30f, rm1 = -1e30f;
        #pragma unroll
        for (int nb = 0; nb < 8; nb++) {
            #pragma unroll
            for (int q = 0; q < 4; q++) s[nb][q] *= SCALE;
            rm0 = fmaxf(rm0, fmaxf(s[nb][0], s[nb][1]));
            rm1 = fmaxf(rm1, fmaxf(s[nb][2], s[nb][3]));
        }
        rm0 = fmaxf(rm0, __shfl_xor_sync(0xffffffffu, rm0, 1));
        rm0 = fmaxf(rm0, __shfl_xor_sync(0xffffffffu, rm0, 2));
        rm1 = fmaxf(rm1, __shfl_xor_sync(0xffffffffu, rm1, 1));
        rm1 = fmaxf(rm1, __shfl_xor_sync(0xffffffffu, rm1, 2));
        float nm0 = fmaxf(m0, rm0), nm1 = fmaxf(m1, rm1);
        float a0 = __expf(m0 - nm0), a1 = __expf(m1 - nm1);
        m0 = nm0; m1 = nm1;

        float sum0 = 0.f, sum1 = 0.f;
        uint32_t pf[4][4];
        #pragma unroll
        for (int nb = 0; nb < 8; nb++) {
            float p00 = __expf(s[nb][0] - nm0);
            float p01 = __expf(s[nb][1] - nm0);
            float p10 = __expf(s[nb][2] - nm1);
            float p11 = __expf(s[nb][3] - nm1);
            sum0 += p00 + p01;
            sum1 += p10 + p11;
            int c = nb >> 1, off = (nb & 1) ? 2 : 0;
            pf[c][off + 0] = packh2(p00, p01);
            pf[c][off + 1] = packh2(p10, p11);
        }
        sum0 += __shfl_xor_sync(0xffffffffu, sum0, 1);
        sum0 += __shfl_xor_sync(0xffffffffu, sum0, 2);
        sum1 += __shfl_xor_sync(0xffffffffu, sum1, 1);
        sum1 += __shfl_xor_sync(0xffffffffu, sum1, 2);
        l0 = l0 * a0 + sum0;
        l1 = l1 * a1 + sum1;
        #pragma unroll
        for (int nb = 0; nb < 8; nb++) {
            o[nb][0] *= a0; o[nb][1] *= a0;
            o[nb][2] *= a1; o[nb][3] *= a1;
        }

        // ---- O += P V ----
        #pragma unroll
        for (int c = 0; c < 4; c++) {
            uint32_t vf[4][4];
            #pragma unroll
            for (int dp = 0; dp < 4; dp++)
                ldsm4t(vf[dp], st + KVT + (uint32_t)((c * 16 + lrow) * RSTR + dp * 32) + lcol);
            #pragma unroll
            for (int dp = 0; dp < 4; dp++) {
                mma_h(o[2 * dp],     pf[c], vf[dp][0], vf[dp][1]);
                mma_h(o[2 * dp + 1], pf[c], vf[dp][2], vf[dp][3]);
            }
        }
        __syncthreads();
        if (it + 2 < 16) issueKV(it + 2);
        CP_COMMIT();
    }

    // ---- epilogue ----
    float inv0 = 1.0f / l0, inv1 = 1.0f / l1;
    int b = bh >> 4, h = bh & 15;
    int nrow = i0 + wid * 16 + (lane >> 2);
    size_t t0 = (size_t)b * SEQ + nrow;
    #pragma unroll
    for (int nb = 0; nb < 8; nb++) {
        int col = h * 64 + nb * 8 + (lane & 3) * 2;
        *(uint32_t*)(O + t0 * DIM + col)       = packh2(o[nb][0] * inv0, o[nb][1] * inv0);
        *(uint32_t*)(O + (t0 + 8) * DIM + col) = packh2(o[nb][2] * inv1, o[nb][3] * inv1);
    }
}

// ----------------------------------------------------------------------------
extern "C" void kernel_launch(void* const* d_in, const int* in_sizes, int n_in,
                              void* d_out, int out_size) {
    const float* x_in   = (const float*)d_in[0];
    const float* ln1_w  = (const float*)d_in[1];
    const float* ln1_b  = (const float*)d_in[2];
    const float* qkv_w  = (const float*)d_in[3];
    const float* qkv_b  = (const float*)d_in[4];
    const float* proj_w = (const float*)d_in[5];
    const float* proj_b = (const float*)d_in[6];
    const float* ln2_w  = (const float*)d_in[7];
    const float* ln2_b  = (const float*)d_in[8];
    const float* mlp_w1 = (const float*)d_in[9];
    const float* mlp_b1 = (const float*)d_in[10];
    const float* mlp_w2 = (const float*)d_in[11];
    const float* mlp_b2 = (const float*)d_in[12];
    float* out = (float*)d_out;

    float *px;
    __half *py, *pa, *ph, *pq, *pk, *pv;
    __half *wq, *wp, *w1, *w2;
    cudaGetSymbolAddress((void**)&px, g_x);
    cudaGetSymbolAddress((void**)&py, g_y);
    cudaGetSymbolAddress((void**)&pa, g_a);
    cudaGetSymbolAddress((void**)&ph, g_h);
    cudaGetSymbolAddress((void**)&pq, g_q);
    cudaGetSymbolAddress((void**)&pk, g_k);
    cudaGetSymbolAddress((void**)&pv, g_v);
    cudaGetSymbolAddress((void**)&wq, g_wq);
    cudaGetSymbolAddress((void**)&wp, g_wp);
    cudaGetSymbolAddress((void**)&w1, g_w1);
    cudaGetSymbolAddress((void**)&w2, g_w2);

    const int SMEMSZ  = 3 * 2 * 128 * 80;              // 61440 B (gemm)
    const int FSMEMSZ = 128 * 144 + 2 * 2 * 64 * 144;  // 55296 B (flash)
    cudaFuncSetAttribute(gemm_mma<2>, cudaFuncAttributeMaxDynamicSharedMemorySize, SMEMSZ);
    cudaFuncSetAttribute(gemm_mma<3>, cudaFuncAttributeMaxDynamicSharedMemorySize, SMEMSZ);
    cudaFuncSetAttribute(gemm_mma<4>, cudaFuncAttributeMaxDynamicSharedMemorySize, SMEMSZ);
    cudaFuncSetAttribute(flash_kernel, cudaFuncAttributeMaxDynamicSharedMemorySize, FSMEMSZ);

    // weight transpose to fp16
    dim3 blk(32, 8);
    wconvert<<<dim3(3 * DIM / 32, DIM / 32, DEPTH), blk>>>(qkv_w,  wq, DIM,  3 * DIM);
    wconvert<<<dim3(DIM / 32,     DIM / 32, DEPTH), blk>>>(proj_w, wp, DIM,  DIM);
    wconvert<<<dim3(MLPD / 32,    DIM / 32, DEPTH), blk>>>(mlp_w1, w1, DIM,  MLPD);
    wconvert<<<dim3(DIM / 32,    MLPD / 32, DEPTH), blk>>>(mlp_w2, w2, MLPD, DIM);

    for (int l = 0; l < DEPTH; l++) {
        size_t oq = (size_t)l * 3 * DIM * DIM;
        size_t op = (size_t)l * DIM * DIM;
        size_t o1 = (size_t)l * MLPD * DIM;
        size_t o2 = (size_t)l * DIM * MLPD;
        const float* xcur = (l == 0) ? x_in : px;          // residual source
        float* xnext = (l == DEPTH - 1) ? out : px;        // final layer -> d_out

        // ---- attention sublayer ----
        ln_half<<<TOK / 8, 256>>>(xcur, ln1_w + (size_t)l * DIM, ln1_b + (size_t)l * DIM, py);
        gemm_mma<4><<<dim3(3 * DIM / 128, TOK / 128), 256, SMEMSZ>>>(
            py, wq + oq, qkv_b + (size_t)l * 3 * DIM, nullptr,
            nullptr, nullptr, pq, pk, pv, TOK, 3 * DIM, DIM);
        flash_kernel<<<dim3(8, BATCH * HEADS), 256, FSMEMSZ>>>(pq, pk, pv, pa);
        gemm_mma<3><<<dim3(DIM / 128, TOK / 128), 256, SMEMSZ>>>(
            pa, wp + op, proj_b + (size_t)l * DIM, xcur,
            px, nullptr, nullptr, nullptr, nullptr, TOK, DIM, DIM);

        // ---- MLP sublayer ----
        ln_half<<<TOK / 8, 256>>>(px, ln2_w + (size_t)l * DIM, ln2_b + (size_t)l * DIM, py);
        gemm_mma<2><<<dim3(MLPD / 128, TOK / 128), 256, SMEMSZ>>>(
            py, w1 + o1, mlp_b1 + (size_t)l * MLPD, nullptr,
            nullptr, ph, nullptr, nullptr, nullptr, TOK, MLPD, DIM);
        gemm_mma<3><<<dim3(DIM / 128, TOK / 128), 256, SMEMSZ>>>(
            ph, w2 + o2, mlp_b2 + (size_t)l * DIM, px,
            xnext, nullptr, nullptr, nullptr, nullptr, TOK, DIM, MLPD);
    }
}